// round 1
// baseline (speedup 1.0000x reference)
#include <cuda_runtime.h>
#include <math.h>

// Problem: x[4096,768] @ W_proj^T + b_proj -> angles (+theta per wire) ->
// closed-form quantum head (cos + prefix products over groups of 8) ->
// expz[4096,768] @ W_comb^T + b_comb -> out[4096,768].
//
// Quantum head closed form (CNOT ring is a linear XOR map on basis bits):
//   expz[w] = prod_{j=0..w} cos(angle_j)  (w>=1)
//   expz[0] = prod_{j=1..7} cos(angle_j)

#define BM 128
#define BN 128
#define BK 16
#define TM 8
#define TN 8
#define THREADS 256

#define M_DIM 4096
#define N_DIM 768
#define K_DIM 768

// Scratch for expz (allocation-free rule: __device__ global)
__device__ float g_expz[M_DIM * N_DIM];

// C = A @ B^T (+bias), A[M,K] row-major, B[N,K] row-major.
// QUANTUM: fuse per-8-column cos + prefix-product transform into epilogue.
template <bool QUANTUM>
__global__ __launch_bounds__(THREADS, 2)
void gemm_nt_kernel(const float* __restrict__ A,
                    const float* __restrict__ B,
                    const float* __restrict__ bias,
                    const float* __restrict__ theta,
                    float* __restrict__ C)
{
    __shared__ float As[BK][BM];
    __shared__ float Bs[BK][BN];

    const int bm = blockIdx.y * BM;
    const int bn = blockIdx.x * BN;
    const int tid = threadIdx.x;
    const int tx = tid & 15;   // 0..15 -> 8 consecutive n each (head-aligned)
    const int ty = tid >> 4;   // 0..15 -> 8 consecutive m each

    float acc[TM][TN];
#pragma unroll
    for (int i = 0; i < TM; i++)
#pragma unroll
        for (int j = 0; j < TN; j++) acc[i][j] = 0.0f;

    for (int k0 = 0; k0 < K_DIM; k0 += BK) {
        // Cooperative load: 128 rows x 16 k, vectorized float4, transposed to smem
#pragma unroll
        for (int i = 0; i < 2; i++) {
            int idx = tid + i * THREADS;     // 0..511
            int row = idx >> 2;              // 0..127
            int c4  = (idx & 3) * 4;         // 0,4,8,12
            float4 av = *(const float4*)(A + (size_t)(bm + row) * K_DIM + k0 + c4);
            As[c4 + 0][row] = av.x;
            As[c4 + 1][row] = av.y;
            As[c4 + 2][row] = av.z;
            As[c4 + 3][row] = av.w;
            float4 bv = *(const float4*)(B + (size_t)(bn + row) * K_DIM + k0 + c4);
            Bs[c4 + 0][row] = bv.x;
            Bs[c4 + 1][row] = bv.y;
            Bs[c4 + 2][row] = bv.z;
            Bs[c4 + 3][row] = bv.w;
        }
        __syncthreads();

#pragma unroll
        for (int kk = 0; kk < BK; kk++) {
            float a_frag[TM], b_frag[TN];
#pragma unroll
            for (int i = 0; i < TM; i += 4)
                *(float4*)&a_frag[i] = *(const float4*)&As[kk][ty * TM + i];
#pragma unroll
            for (int j = 0; j < TN; j += 4)
                *(float4*)&b_frag[j] = *(const float4*)&Bs[kk][tx * TN + j];
#pragma unroll
            for (int i = 0; i < TM; i++)
#pragma unroll
                for (int j = 0; j < TN; j++)
                    acc[i][j] = fmaf(a_frag[i], b_frag[j], acc[i][j]);
        }
        __syncthreads();
    }

    // Epilogue
    const int n0 = bn + tx * TN;   // multiple of 8 -> wire index == j
#pragma unroll
    for (int i = 0; i < TM; i++) {
        const int m = bm + ty * TM + i;
        float* crow = C + (size_t)m * N_DIM + n0;
        if (QUANTUM) {
            float c[8];
#pragma unroll
            for (int j = 0; j < 8; j++) {
                float ang = acc[i][j] + bias[n0 + j] + theta[j];
                c[j] = cosf(ang);
            }
            float out[8];
            float p = c[0];
#pragma unroll
            for (int j = 1; j < 8; j++) { p *= c[j]; out[j] = p; }
            float s = c[1];
#pragma unroll
            for (int j = 2; j < 8; j++) s *= c[j];
            out[0] = s;
            *(float4*)(crow + 0) = make_float4(out[0], out[1], out[2], out[3]);
            *(float4*)(crow + 4) = make_float4(out[4], out[5], out[6], out[7]);
        } else {
            float4 v0, v1;
            v0.x = acc[i][0] + bias[n0 + 0];
            v0.y = acc[i][1] + bias[n0 + 1];
            v0.z = acc[i][2] + bias[n0 + 2];
            v0.w = acc[i][3] + bias[n0 + 3];
            v1.x = acc[i][4] + bias[n0 + 4];
            v1.y = acc[i][5] + bias[n0 + 5];
            v1.z = acc[i][6] + bias[n0 + 6];
            v1.w = acc[i][7] + bias[n0 + 7];
            *(float4*)(crow + 0) = v0;
            *(float4*)(crow + 4) = v1;
        }
    }
}

extern "C" void kernel_launch(void* const* d_in, const int* in_sizes, int n_in,
                              void* d_out, int out_size)
{
    const float* x      = (const float*)d_in[0];  // [8,512,768] -> [4096,768]
    const float* W_proj = (const float*)d_in[1];  // [768,768]
    const float* b_proj = (const float*)d_in[2];  // [768]
    const float* theta  = (const float*)d_in[3];  // [8]
    const float* W_comb = (const float*)d_in[4];  // [768,768]
    const float* b_comb = (const float*)d_in[5];  // [768]
    float* out = (float*)d_out;                   // [4096,768]

    float* expz = nullptr;
    cudaGetSymbolAddress((void**)&expz, g_expz);

    dim3 grid(N_DIM / BN, M_DIM / BM);  // (6, 32) = 192 CTAs
    dim3 block(THREADS);

    gemm_nt_kernel<true><<<grid, block>>>(x, W_proj, b_proj, theta, expz);
    gemm_nt_kernel<false><<<grid, block>>>(expz, W_comb, b_comb, nullptr, out);
}

// round 3
// speedup vs baseline: 2.0078x; 2.0078x over previous
#include <cuda_runtime.h>
#include <cuda_bf16.h>
#include <math.h>
#include <stdint.h>

// out = ((cos-product head)(x @ Wp^T + bp + theta)) @ Wc^T + bc
// Quantum head closed form (CNOT ring = linear XOR map on basis bits):
//   expz[w] = prod_{j=0..w} cos(ang_j)  (w>=1);  expz[0] = prod_{j=1..7} cos(ang_j)
//
// Tensor path: legacy mma.sync m16n8k16 bf16 (sm_80 ISA -> HMMA; tcgen05 PTX
// is rejected because the harness PTX target is plain sm_103).
// Accuracy: bf16 hi/lo split, 3 terms folded into one K=2304 GEMM:
//   A2 = [a_hi | a_hi | a_lo],  B2 = [b_hi | b_lo | b_hi]
//   A2 @ B2^T = hh + hl + lh  (drop lo*lo ~ 2^-18)

#define M_DIM 4096
#define N_DIM 768
#define KD    768
#define K2    2304
#define BM    128
#define BN    128
#define BK    32
#define NITER (K2 / BK)   // 72
#define THREADS 256

#define ROW_B   80                  // 64B data + 16B pad per 32-half row
#define TILE_B  (BM * ROW_B)        // 10240
#define STAGE_B (2 * TILE_B)        // 20480 (A + B)
#define SMEM_PIPE (3 * STAGE_B)     // 61440
#define CPAD    (BN + 4)
#define SMEM_EPI (BM * CPAD * 4)    // 67584
#define SMEM_SZ  SMEM_EPI           // max(pipe, epi)

// ---- device scratch (allocation-free rule) ----
__device__ __nv_bfloat16 g_A2[(size_t)M_DIM * K2];
__device__ __nv_bfloat16 g_Bp[(size_t)N_DIM * K2];
__device__ __nv_bfloat16 g_Bc[(size_t)N_DIM * K2];
__device__ __nv_bfloat16 g_E2[(size_t)M_DIM * K2];

// ---- helpers ----
__device__ __forceinline__ uint32_t smem_u32(const void* p) {
    uint32_t a;
    asm("{ .reg .u64 t; cvta.to.shared.u64 t, %1; cvt.u32.u64 %0, t; }" : "=r"(a) : "l"(p));
    return a;
}
__device__ __forceinline__ void cp_async16(uint32_t dst, const void* src) {
    asm volatile("cp.async.cg.shared.global [%0], [%1], 16;" :: "r"(dst), "l"(src));
}
__device__ __forceinline__ void ldsm4(uint32_t* r, uint32_t addr) {
    asm volatile("ldmatrix.sync.aligned.m8n8.x4.shared.b16 {%0,%1,%2,%3}, [%4];"
                 : "=r"(r[0]), "=r"(r[1]), "=r"(r[2]), "=r"(r[3]) : "r"(addr));
}
__device__ __forceinline__ void mma_bf16(float* c, const uint32_t* a, uint32_t b0, uint32_t b1) {
    asm volatile(
        "mma.sync.aligned.m16n8k16.row.col.f32.bf16.bf16.f32 "
        "{%0,%1,%2,%3}, {%4,%5,%6,%7}, {%8,%9}, {%0,%1,%2,%3};"
        : "+f"(c[0]), "+f"(c[1]), "+f"(c[2]), "+f"(c[3])
        : "r"(a[0]), "r"(a[1]), "r"(a[2]), "r"(a[3]), "r"(b0), "r"(b1));
}
__device__ __forceinline__ void split_bf16x2(float f0, float f1, uint32_t& hi, uint32_t& lo) {
    __nv_bfloat162 hh, ll;
    hh.x = __float2bfloat16(f0);
    hh.y = __float2bfloat16(f1);
    ll.x = __float2bfloat16(f0 - __bfloat162float(hh.x));
    ll.y = __float2bfloat16(f1 - __bfloat162float(hh.y));
    hi = *(uint32_t*)&hh;
    lo = *(uint32_t*)&ll;
}

// ---- fp32 -> duplicated/split bf16 layout: dst rows of K2,
//      hi at cols [0,768) and [dup2), lo at [lo3) ----
__global__ void split_kernel(const float* __restrict__ x,
                             const float* __restrict__ wp,
                             const float* __restrict__ wc) {
    const int n4x = M_DIM * KD / 4;
    const int n4w = N_DIM * KD / 4;
    int i = blockIdx.x * blockDim.x + threadIdx.x;
    const float* src; __nv_bfloat16* dst; int j; int hidup, lopos;
    if (i < n4x) {
        src = x;  dst = g_A2; j = i; hidup = KD; lopos = 2 * KD;        // A2=[hi|hi|lo]
    } else if (i < n4x + n4w) {
        src = wp; dst = g_Bp; j = i - n4x; hidup = 2 * KD; lopos = KD;  // B2=[hi|lo|hi]
    } else if (i < n4x + 2 * n4w) {
        src = wc; dst = g_Bc; j = i - n4x - n4w; hidup = 2 * KD; lopos = KD;
    } else return;
    int r = j / (KD / 4);
    int c = (j % (KD / 4)) * 4;
    float4 v = ((const float4*)src)[j];
    uint32_t h0, l0, h1, l1;
    split_bf16x2(v.x, v.y, h0, l0);
    split_bf16x2(v.z, v.w, h1, l1);
    size_t base = (size_t)r * K2 + c;
    *(uint2*)(dst + base)         = make_uint2(h0, h1);
    *(uint2*)(dst + base + hidup) = make_uint2(h0, h1);
    *(uint2*)(dst + base + lopos) = make_uint2(l0, l1);
}

// ---- GEMM: C[M,N](fp32-acc) = A2 @ B2^T, 3-stage cp.async, mma.sync bf16 ----
template <bool QUANTUM>
__global__ __launch_bounds__(THREADS, 2)
void mma_gemm(const __nv_bfloat16* __restrict__ A2,
              const __nv_bfloat16* __restrict__ B2,
              const float* __restrict__ bias,
              const float* __restrict__ theta,
              __nv_bfloat16* __restrict__ E2,
              float* __restrict__ out)
{
    extern __shared__ char smem[];
    const uint32_t sb = smem_u32(smem);
    const int tid = threadIdx.x;
    const int l = tid & 31;
    const int wid = tid >> 5;
    const int warp_m = wid & 3;   // 4 row-warps * 32 = 128
    const int warp_n = wid >> 2;  // 2 col-warps * 64 = 128
    const int bm = blockIdx.y * BM;
    const int bn = blockIdx.x * BN;

    // cooperative load indices: 512 16B chunks per matrix, 2 per thread
    const int ldr0 = tid >> 2, ldc0 = (tid & 3) * 16;
    const int ldr1 = (tid + 256) >> 2, ldc1 = ldc0;  // same chunk col, +64 rows

    float acc[2][8][4];
#pragma unroll
    for (int mi = 0; mi < 2; mi++)
#pragma unroll
        for (int ni = 0; ni < 8; ni++)
#pragma unroll
            for (int q = 0; q < 4; q++) acc[mi][ni][q] = 0.0f;

    // ldmatrix lane offset within a 16x16 (x4) block
    const uint32_t lane_off = (uint32_t)((l & 15) * ROW_B + (l >> 4) * 16);
    const uint32_t a_warp = (uint32_t)(warp_m * 32 * ROW_B);
    const uint32_t b_warp = (uint32_t)(warp_n * 64 * ROW_B);

    auto load_stage = [&](int s, int k0) {
        uint32_t sA = sb + s * STAGE_B;
        uint32_t sB = sA + TILE_B;
        const __nv_bfloat16* gA = A2 + (size_t)(bm + ldr0) * K2 + k0;
        const __nv_bfloat16* gB = B2 + (size_t)(bn + ldr0) * K2 + k0;
        cp_async16(sA + ldr0 * ROW_B + ldc0, gA + ldc0 / 2);
        cp_async16(sB + ldr0 * ROW_B + ldc0, gB + ldc0 / 2);
        const __nv_bfloat16* gA1 = A2 + (size_t)(bm + ldr1) * K2 + k0;
        const __nv_bfloat16* gB1 = B2 + (size_t)(bn + ldr1) * K2 + k0;
        cp_async16(sA + ldr1 * ROW_B + ldc1, gA1 + ldc1 / 2);
        cp_async16(sB + ldr1 * ROW_B + ldc1, gB1 + ldc1 / 2);
    };

    load_stage(0, 0);
    asm volatile("cp.async.commit_group;");
    load_stage(1, BK);
    asm volatile("cp.async.commit_group;");

    for (int kt = 0; kt < NITER; kt++) {
        asm volatile("cp.async.wait_group 1;");
        __syncthreads();

        if (kt + 2 < NITER) load_stage((kt + 2) % 3, (kt + 2) * BK);
        asm volatile("cp.async.commit_group;");

        const int s = kt % 3;
        const uint32_t sA = sb + s * STAGE_B + a_warp + lane_off;
        const uint32_t sB = sb + s * STAGE_B + TILE_B + b_warp + lane_off;
#pragma unroll
        for (int ksub = 0; ksub < 2; ksub++) {
            uint32_t a[2][4], b[4][4];
#pragma unroll
            for (int mi = 0; mi < 2; mi++)
                ldsm4(a[mi], sA + mi * 16 * ROW_B + ksub * 32);
#pragma unroll
            for (int q = 0; q < 4; q++)
                ldsm4(b[q], sB + q * 16 * ROW_B + ksub * 32);
#pragma unroll
            for (int mi = 0; mi < 2; mi++)
#pragma unroll
                for (int q = 0; q < 4; q++) {
                    mma_bf16(acc[mi][2 * q],     a[mi], b[q][0], b[q][2]);
                    mma_bf16(acc[mi][2 * q + 1], a[mi], b[q][1], b[q][3]);
                }
        }
        __syncthreads();
    }
    asm volatile("cp.async.wait_group 0;");
    __syncthreads();

    if (QUANTUM) {
        // stage accums through smem, then closed-form quantum head per 8-col group
        float* Cs = (float*)smem;
#pragma unroll
        for (int mi = 0; mi < 2; mi++)
#pragma unroll
            for (int ni = 0; ni < 8; ni++) {
                int row = warp_m * 32 + mi * 16 + (l >> 2);
                int col = warp_n * 64 + ni * 8 + (l & 3) * 2;
                *(float2*)&Cs[row * CPAD + col]       = make_float2(acc[mi][ni][0], acc[mi][ni][1]);
                *(float2*)&Cs[(row + 8) * CPAD + col] = make_float2(acc[mi][ni][2], acc[mi][ni][3]);
            }
        __syncthreads();

        float th[8];
#pragma unroll
        for (int j = 0; j < 8; j++) th[j] = theta[j];

#pragma unroll
        for (int i = 0; i < 8; i++) {
            int g = tid + i * THREADS;      // 0..2047
            int r = g >> 4;                  // tile row
            int h = g & 15;                  // head slot in tile
            int nn = bn + h * 8;             // global col of head base
            const float* src = &Cs[r * CPAD + h * 8];
            float cc[8];
#pragma unroll
            for (int j = 0; j < 8; j++)
                cc[j] = cosf(src[j] + bias[nn + j] + th[j]);
            float o[8];
            float p = cc[0];
#pragma unroll
            for (int j = 1; j < 8; j++) { p *= cc[j]; o[j] = p; }
            float sp = cc[1];
#pragma unroll
            for (int j = 2; j < 8; j++) sp *= cc[j];
            o[0] = sp;
            uint32_t hi[4], lo[4];
#pragma unroll
            for (int q = 0; q < 4; q++) split_bf16x2(o[2 * q], o[2 * q + 1], hi[q], lo[q]);
            size_t base = (size_t)(bm + r) * K2 + nn;
            uint4 hv = make_uint4(hi[0], hi[1], hi[2], hi[3]);
            *(uint4*)(E2 + base)          = hv;   // [eh | eh | el]
            *(uint4*)(E2 + base + KD)     = hv;
            *(uint4*)(E2 + base + 2 * KD) = make_uint4(lo[0], lo[1], lo[2], lo[3]);
        }
    } else {
        // bias add + direct fp32 store
#pragma unroll
        for (int mi = 0; mi < 2; mi++)
#pragma unroll
            for (int ni = 0; ni < 8; ni++) {
                int row = bm + warp_m * 32 + mi * 16 + (l >> 2);
                int col = bn + warp_n * 64 + ni * 8 + (l & 3) * 2;
                float b0 = bias[col], b1 = bias[col + 1];
                *(float2*)&out[(size_t)row * N_DIM + col] =
                    make_float2(acc[mi][ni][0] + b0, acc[mi][ni][1] + b1);
                *(float2*)&out[(size_t)(row + 8) * N_DIM + col] =
                    make_float2(acc[mi][ni][2] + b0, acc[mi][ni][3] + b1);
            }
    }
}

extern "C" void kernel_launch(void* const* d_in, const int* in_sizes, int n_in,
                              void* d_out, int out_size)
{
    const float* x      = (const float*)d_in[0];
    const float* W_proj = (const float*)d_in[1];
    const float* b_proj = (const float*)d_in[2];
    const float* theta  = (const float*)d_in[3];
    const float* W_comb = (const float*)d_in[4];
    const float* b_comb = (const float*)d_in[5];
    float* out = (float*)d_out;

    static int configured = 0;
    cudaFuncSetAttribute(mma_gemm<true>,  cudaFuncAttributeMaxDynamicSharedMemorySize, SMEM_SZ);
    cudaFuncSetAttribute(mma_gemm<false>, cudaFuncAttributeMaxDynamicSharedMemorySize, SMEM_SZ);
    (void)configured;

    __nv_bfloat16 *A2, *Bp, *Bc, *E2;
    cudaGetSymbolAddress((void**)&A2, g_A2);
    cudaGetSymbolAddress((void**)&Bp, g_Bp);
    cudaGetSymbolAddress((void**)&Bc, g_Bc);
    cudaGetSymbolAddress((void**)&E2, g_E2);

    const int total4 = M_DIM * KD / 4 + 2 * (N_DIM * KD / 4);
    split_kernel<<<(total4 + 255) / 256, 256>>>(x, W_proj, W_comb);

    dim3 grid(N_DIM / BN, M_DIM / BM);  // (6, 32) = 192 CTAs
    mma_gemm<true><<<grid, THREADS, SMEM_SZ>>>(A2, Bp, b_proj, theta, E2, nullptr);
    mma_gemm<false><<<grid, THREADS, SMEM_SZ>>>(E2, Bc, b_comb, nullptr, nullptr, out);
}

// round 4
// speedup vs baseline: 2.4391x; 1.2148x over previous
#include <cuda_runtime.h>
#include <cuda_bf16.h>
#include <math.h>
#include <stdint.h>

// out = ((cos-product head)(x @ Wp^T + bp + theta)) @ Wc^T + bc
// Quantum head closed form (CNOT ring = linear XOR map on basis bits):
//   expz[w] = prod_{j=0..w} cos(ang_j)  (w>=1);  expz[0] = prod_{j=1..7} cos(ang_j)
//
// Tensor path: mma.sync m16n8k16 bf16 (HMMA; tcgen05 PTX rejected at sm_103 target).
// Accuracy: bf16 hi/lo split, 3 terms folded into one K=2304 GEMM:
//   A2 = [a_hi | a_hi | a_lo],  B2 = [b_hi | b_lo | b_hi]  ->  hh + hl + lh

#define M_DIM 4096
#define N_DIM 768
#define KD    768
#define K2    2304
#define BM    128
#define BN    192
#define BK    64
#define NITER (K2 / BK)        // 36
#define THREADS 256

#define AROWS   BM
#define TROWS   (BM + BN)      // 320 rows per stage (A then B)
#define STAGE_B (TROWS * 128)  // 40960 (swizzled 128B rows, no pad)
#define SMEM_PIPE (3 * STAGE_B)            // 122880
#define CPAD    (BN + 4)
#define SMEM_EPI (BM * CPAD * 4)           // 100352
#define SMEM_SZ  SMEM_PIPE

// ---- device scratch (allocation-free rule) ----
__device__ __nv_bfloat16 g_A2[(size_t)M_DIM * K2];
__device__ __nv_bfloat16 g_Bp[(size_t)N_DIM * K2];
__device__ __nv_bfloat16 g_Bc[(size_t)N_DIM * K2];
__device__ __nv_bfloat16 g_E2[(size_t)M_DIM * K2];

// ---- helpers ----
__device__ __forceinline__ uint32_t smem_u32(const void* p) {
    uint32_t a;
    asm("{ .reg .u64 t; cvta.to.shared.u64 t, %1; cvt.u32.u64 %0, t; }" : "=r"(a) : "l"(p));
    return a;
}
__device__ __forceinline__ void cp_async16(uint32_t dst, const void* src) {
    asm volatile("cp.async.cg.shared.global [%0], [%1], 16;" :: "r"(dst), "l"(src));
}
__device__ __forceinline__ void ldsm4(uint32_t* r, uint32_t addr) {
    asm volatile("ldmatrix.sync.aligned.m8n8.x4.shared.b16 {%0,%1,%2,%3}, [%4];"
                 : "=r"(r[0]), "=r"(r[1]), "=r"(r[2]), "=r"(r[3]) : "r"(addr));
}
__device__ __forceinline__ void mma_bf16(float* c, const uint32_t* a, uint32_t b0, uint32_t b1) {
    asm volatile(
        "mma.sync.aligned.m16n8k16.row.col.f32.bf16.bf16.f32 "
        "{%0,%1,%2,%3}, {%4,%5,%6,%7}, {%8,%9}, {%0,%1,%2,%3};"
        : "+f"(c[0]), "+f"(c[1]), "+f"(c[2]), "+f"(c[3])
        : "r"(a[0]), "r"(a[1]), "r"(a[2]), "r"(a[3]), "r"(b0), "r"(b1));
}
__device__ __forceinline__ void split_bf16x2(float f0, float f1, uint32_t& hi, uint32_t& lo) {
    __nv_bfloat162 hh, ll;
    hh.x = __float2bfloat16(f0);
    hh.y = __float2bfloat16(f1);
    ll.x = __float2bfloat16(f0 - __bfloat162float(hh.x));
    ll.y = __float2bfloat16(f1 - __bfloat162float(hh.y));
    hi = *(uint32_t*)&hh;
    lo = *(uint32_t*)&ll;
}

// ---- fp32 -> duplicated/split bf16; 8 floats per thread, 16B stores ----
__global__ void split_kernel(const float* __restrict__ x,
                             const float* __restrict__ wp,
                             const float* __restrict__ wc) {
    const int n8x = M_DIM * KD / 8;
    const int n8w = N_DIM * KD / 8;
    int i = blockIdx.x * blockDim.x + threadIdx.x;
    const float* src; __nv_bfloat16* dst; int j; int hidup, lopos;
    if (i < n8x) {
        src = x;  dst = g_A2; j = i; hidup = KD; lopos = 2 * KD;        // [hi|hi|lo]
    } else if (i < n8x + n8w) {
        src = wp; dst = g_Bp; j = i - n8x; hidup = 2 * KD; lopos = KD;  // [hi|lo|hi]
    } else if (i < n8x + 2 * n8w) {
        src = wc; dst = g_Bc; j = i - n8x - n8w; hidup = 2 * KD; lopos = KD;
    } else return;
    int r = j / (KD / 8);
    int c = (j % (KD / 8)) * 8;
    float4 v0 = ((const float4*)src)[j * 2];
    float4 v1 = ((const float4*)src)[j * 2 + 1];
    uint32_t h[4], l[4];
    split_bf16x2(v0.x, v0.y, h[0], l[0]);
    split_bf16x2(v0.z, v0.w, h[1], l[1]);
    split_bf16x2(v1.x, v1.y, h[2], l[2]);
    split_bf16x2(v1.z, v1.w, h[3], l[3]);
    size_t base = (size_t)r * K2 + c;
    uint4 hv = make_uint4(h[0], h[1], h[2], h[3]);
    uint4 lv = make_uint4(l[0], l[1], l[2], l[3]);
    *(uint4*)(dst + base)         = hv;
    *(uint4*)(dst + base + hidup) = hv;
    *(uint4*)(dst + base + lopos) = lv;
}

// ---- GEMM: C[M,N](fp32-acc) = A2 @ B2^T ----
// 128x192 CTA tile, 8 warps as 2x4 (64x48 warp tiles), BK=64, 3-stage cp.async,
// XOR-swizzled 128B smem rows (conflict-free stores + ldmatrix).
template <bool QUANTUM>
__global__ __launch_bounds__(THREADS)
void mma_gemm(const __nv_bfloat16* __restrict__ A2,
              const __nv_bfloat16* __restrict__ B2,
              const float* __restrict__ bias,
              const float* __restrict__ theta,
              __nv_bfloat16* __restrict__ E2,
              float* __restrict__ out)
{
    extern __shared__ char smem[];
    const uint32_t sb = smem_u32(smem);
    const int tid = threadIdx.x;
    const int l = tid & 31;
    const int wid = tid >> 5;
    const int warp_m = wid & 1;    // 2 x 64 rows
    const int warp_n = wid >> 1;   // 4 x 48 cols
    const int bm = blockIdx.y * BM;
    const int bn = blockIdx.x * BN;

    float acc[4][6][4];
#pragma unroll
    for (int mi = 0; mi < 4; mi++)
#pragma unroll
        for (int ni = 0; ni < 6; ni++)
#pragma unroll
            for (int q = 0; q < 4; q++) acc[mi][ni][q] = 0.0f;

    // cooperative load: 2560 16B chunks/stage, 10 per thread
    auto load_stage = [&](int s, int k0) {
        uint32_t stage = sb + s * STAGE_B;
#pragma unroll
        for (int i = 0; i < 10; i++) {
            int id = tid + i * THREADS;
            int row = id >> 3;
            int c = id & 7;
            int cs = c ^ (row & 7);
            uint32_t dst = stage + row * 128 + cs * 16;
            const __nv_bfloat16* g;
            if (row < AROWS) g = A2 + (size_t)(bm + row) * K2 + k0 + c * 8;
            else             g = B2 + (size_t)(bn + row - AROWS) * K2 + k0 + c * 8;
            cp_async16(dst, g);
        }
    };

    load_stage(0, 0);
    asm volatile("cp.async.commit_group;");
    load_stage(1, BK);
    asm volatile("cp.async.commit_group;");

    // ldmatrix swizzled column index (row&7 == l&7 for 16-aligned row bases)
    const int lr = l & 15;
    const int lc = l >> 4;
    const int lx = l & 7;

    for (int kt = 0; kt < NITER; kt++) {
        asm volatile("cp.async.wait_group 1;");
        __syncthreads();

        if (kt + 2 < NITER) load_stage((kt + 2) % 3, (kt + 2) * BK);
        asm volatile("cp.async.commit_group;");

        const uint32_t stage = sb + (kt % 3) * STAGE_B;
#pragma unroll
        for (int ksub = 0; ksub < 4; ksub++) {
            const int cs = (2 * ksub + lc) ^ lx;
            uint32_t a[4][4], b[3][4];
#pragma unroll
            for (int mi = 0; mi < 4; mi++) {
                int row = warp_m * 64 + mi * 16 + lr;
                ldsm4(a[mi], stage + row * 128 + cs * 16);
            }
#pragma unroll
            for (int q = 0; q < 3; q++) {
                int row = AROWS + warp_n * 48 + q * 16 + lr;
                ldsm4(b[q], stage + row * 128 + cs * 16);
            }
#pragma unroll
            for (int mi = 0; mi < 4; mi++)
#pragma unroll
                for (int q = 0; q < 3; q++) {
                    mma_bf16(acc[mi][2 * q],     a[mi], b[q][0], b[q][2]);
                    mma_bf16(acc[mi][2 * q + 1], a[mi], b[q][1], b[q][3]);
                }
        }
        __syncthreads();
    }
    asm volatile("cp.async.wait_group 0;");
    __syncthreads();

    if (QUANTUM) {
        // stage accums through smem, then closed-form quantum head per 8-col group
        float* Cs = (float*)smem;
#pragma unroll
        for (int mi = 0; mi < 4; mi++)
#pragma unroll
            for (int ni = 0; ni < 6; ni++) {
                int row = warp_m * 64 + mi * 16 + (l >> 2);
                int col = warp_n * 48 + ni * 8 + (l & 3) * 2;
                *(float2*)&Cs[row * CPAD + col]       = make_float2(acc[mi][ni][0], acc[mi][ni][1]);
                *(float2*)&Cs[(row + 8) * CPAD + col] = make_float2(acc[mi][ni][2], acc[mi][ni][3]);
            }
        __syncthreads();

        float th[8];
#pragma unroll
        for (int j = 0; j < 8; j++) th[j] = theta[j];

        // 128 rows x 24 heads = 3072 tasks, 12 per thread
#pragma unroll
        for (int i = 0; i < 12; i++) {
            int g = tid + i * THREADS;
            int r = g / 24;
            int h = g - r * 24;
            int nn = bn + h * 8;
            const float* src = &Cs[r * CPAD + h * 8];
            float cc[8];
#pragma unroll
            for (int j = 0; j < 8; j++)
                cc[j] = cosf(src[j] + bias[nn + j] + th[j]);
            float o[8];
            float p = cc[0];
#pragma unroll
            for (int j = 1; j < 8; j++) { p *= cc[j]; o[j] = p; }
            float sp = cc[1];
#pragma unroll
            for (int j = 2; j < 8; j++) sp *= cc[j];
            o[0] = sp;
            uint32_t hi[4], lo[4];
#pragma unroll
            for (int q = 0; q < 4; q++) split_bf16x2(o[2 * q], o[2 * q + 1], hi[q], lo[q]);
            size_t base = (size_t)(bm + r) * K2 + nn;
            uint4 hv = make_uint4(hi[0], hi[1], hi[2], hi[3]);
            *(uint4*)(E2 + base)          = hv;   // [eh | eh | el]
            *(uint4*)(E2 + base + KD)     = hv;
            *(uint4*)(E2 + base + 2 * KD) = make_uint4(lo[0], lo[1], lo[2], lo[3]);
        }
    } else {
        // bias add + direct fp32 store
#pragma unroll
        for (int mi = 0; mi < 4; mi++)
#pragma unroll
            for (int ni = 0; ni < 6; ni++) {
                int row = bm + warp_m * 64 + mi * 16 + (l >> 2);
                int col = bn + warp_n * 48 + ni * 8 + (l & 3) * 2;
                float b0 = bias[col], b1 = bias[col + 1];
                *(float2*)&out[(size_t)row * N_DIM + col] =
                    make_float2(acc[mi][ni][0] + b0, acc[mi][ni][1] + b1);
                *(float2*)&out[(size_t)(row + 8) * N_DIM + col] =
                    make_float2(acc[mi][ni][2] + b0, acc[mi][ni][3] + b1);
            }
    }
}

extern "C" void kernel_launch(void* const* d_in, const int* in_sizes, int n_in,
                              void* d_out, int out_size)
{
    const float* x      = (const float*)d_in[0];
    const float* W_proj = (const float*)d_in[1];
    const float* b_proj = (const float*)d_in[2];
    const float* theta  = (const float*)d_in[3];
    const float* W_comb = (const float*)d_in[4];
    const float* b_comb = (const float*)d_in[5];
    float* out = (float*)d_out;

    cudaFuncSetAttribute(mma_gemm<true>,  cudaFuncAttributeMaxDynamicSharedMemorySize, SMEM_SZ);
    cudaFuncSetAttribute(mma_gemm<false>, cudaFuncAttributeMaxDynamicSharedMemorySize, SMEM_SZ);

    __nv_bfloat16 *A2, *Bp, *Bc, *E2;
    cudaGetSymbolAddress((void**)&A2, g_A2);
    cudaGetSymbolAddress((void**)&Bp, g_Bp);
    cudaGetSymbolAddress((void**)&Bc, g_Bc);
    cudaGetSymbolAddress((void**)&E2, g_E2);

    const int total8 = M_DIM * KD / 8 + 2 * (N_DIM * KD / 8);
    split_kernel<<<(total8 + 255) / 256, 256>>>(x, W_proj, W_comb);

    dim3 grid(N_DIM / BN, M_DIM / BM);  // (4, 32) = 128 CTAs, single wave
    mma_gemm<true><<<grid, THREADS, SMEM_SZ>>>(A2, Bp, b_proj, theta, E2, nullptr);
    mma_gemm<false><<<grid, THREADS, SMEM_SZ>>>(E2, Bc, b_comb, nullptr, nullptr, out);
}

// round 5
// speedup vs baseline: 2.6624x; 1.0915x over previous
#include <cuda_runtime.h>
#include <cuda_bf16.h>
#include <math.h>
#include <stdint.h>

// out = ((cos-product head)(x @ Wp^T + bp + theta)) @ Wc^T + bc
// Quantum head closed form (CNOT ring = linear XOR map on basis bits):
//   expz[w] = prod_{j=0..w} cos(ang_j)  (w>=1);  expz[0] = prod_{j=1..7} cos(ang_j)
//
// Tensor path: mma.sync m16n8k16 bf16 (HMMA; tcgen05 PTX rejected at sm_103 target).
// Accuracy: bf16 hi/lo split, 3 terms as one logical K=2304 GEMM:
//   term region 0: A_hi @ B_hi, region 1: A_hi @ B_lo, region 2: A_lo @ B_hi
// Regions are mapped onto plain hi/lo arrays at load time (no duplication).

#define M_DIM 4096
#define N_DIM 768
#define KD    768
#define K2    2304
#define BM    128
#define BN    192
#define BK    64
#define NITER (K2 / BK)        // 36
#define THREADS 256
#define NSTAGE 4

#define AROWS   BM
#define TROWS   (BM + BN)      // 320 rows per stage (A then B)
#define STAGE_B (TROWS * 128)  // 40960 (swizzled 128B rows)
#define SMEM_SZ (NSTAGE * STAGE_B)   // 163840
#define CPAD    (BN + 4)

// ---- device scratch (allocation-free rule) ----
__device__ __nv_bfloat16 g_Ah[(size_t)M_DIM * KD], g_Al[(size_t)M_DIM * KD];
__device__ __nv_bfloat16 g_Bph[(size_t)N_DIM * KD], g_Bpl[(size_t)N_DIM * KD];
__device__ __nv_bfloat16 g_Bch[(size_t)N_DIM * KD], g_Bcl[(size_t)N_DIM * KD];
__device__ __nv_bfloat16 g_Eh[(size_t)M_DIM * KD], g_El[(size_t)M_DIM * KD];

// ---- helpers ----
__device__ __forceinline__ uint32_t smem_u32(const void* p) {
    uint32_t a;
    asm("{ .reg .u64 t; cvta.to.shared.u64 t, %1; cvt.u32.u64 %0, t; }" : "=r"(a) : "l"(p));
    return a;
}
__device__ __forceinline__ void cp_async16(uint32_t dst, const void* src) {
    asm volatile("cp.async.cg.shared.global [%0], [%1], 16;" :: "r"(dst), "l"(src));
}
__device__ __forceinline__ void ldsm4(uint32_t* r, uint32_t addr) {
    asm volatile("ldmatrix.sync.aligned.m8n8.x4.shared.b16 {%0,%1,%2,%3}, [%4];"
                 : "=r"(r[0]), "=r"(r[1]), "=r"(r[2]), "=r"(r[3]) : "r"(addr));
}
__device__ __forceinline__ void mma_bf16(float* c, const uint32_t* a, uint32_t b0, uint32_t b1) {
    asm volatile(
        "mma.sync.aligned.m16n8k16.row.col.f32.bf16.bf16.f32 "
        "{%0,%1,%2,%3}, {%4,%5,%6,%7}, {%8,%9}, {%0,%1,%2,%3};"
        : "+f"(c[0]), "+f"(c[1]), "+f"(c[2]), "+f"(c[3])
        : "r"(a[0]), "r"(a[1]), "r"(a[2]), "r"(a[3]), "r"(b0), "r"(b1));
}
__device__ __forceinline__ void split_bf16x2(float f0, float f1, uint32_t& hi, uint32_t& lo) {
    __nv_bfloat162 hh, ll;
    hh.x = __float2bfloat16(f0);
    hh.y = __float2bfloat16(f1);
    ll.x = __float2bfloat16(f0 - __bfloat162float(hh.x));
    ll.y = __float2bfloat16(f1 - __bfloat162float(hh.y));
    hi = *(uint32_t*)&hh;
    lo = *(uint32_t*)&ll;
}

// ---- fp32 -> bf16 hi/lo; 8 floats per thread, 16B stores ----
__global__ void split_kernel(const float* __restrict__ x,
                             const float* __restrict__ wp,
                             const float* __restrict__ wc) {
    const int n8x = M_DIM * KD / 8;
    const int n8w = N_DIM * KD / 8;
    int i = blockIdx.x * blockDim.x + threadIdx.x;
    const float* src; __nv_bfloat16 *hi, *lo; int j;
    if (i < n8x)              { src = x;  hi = g_Ah;  lo = g_Al;  j = i; }
    else if (i < n8x + n8w)   { src = wp; hi = g_Bph; lo = g_Bpl; j = i - n8x; }
    else if (i < n8x + 2*n8w) { src = wc; hi = g_Bch; lo = g_Bcl; j = i - n8x - n8w; }
    else return;
    float4 v0 = ((const float4*)src)[j * 2];
    float4 v1 = ((const float4*)src)[j * 2 + 1];
    uint32_t h[4], l[4];
    split_bf16x2(v0.x, v0.y, h[0], l[0]);
    split_bf16x2(v0.z, v0.w, h[1], l[1]);
    split_bf16x2(v1.x, v1.y, h[2], l[2]);
    split_bf16x2(v1.z, v1.w, h[3], l[3]);
    ((uint4*)hi)[j] = make_uint4(h[0], h[1], h[2], h[3]);
    ((uint4*)lo)[j] = make_uint4(l[0], l[1], l[2], l[3]);
}

// ---- GEMM: C[M,N](fp32) = sum over 3 split-term regions of A @ B^T ----
// 128x192 CTA tile, 8 warps as 2x4 (64x48 warp tiles), BK=64, 4-stage cp.async,
// ONE __syncthreads per iter, XOR-swizzled 128B smem rows.
template <bool QUANTUM>
__global__ __launch_bounds__(THREADS)
void mma_gemm(const __nv_bfloat16* __restrict__ Ah, const __nv_bfloat16* __restrict__ Al,
              const __nv_bfloat16* __restrict__ Bh, const __nv_bfloat16* __restrict__ Bl,
              const float* __restrict__ bias,
              const float* __restrict__ theta,
              __nv_bfloat16* __restrict__ Eh, __nv_bfloat16* __restrict__ El,
              float* __restrict__ out)
{
    extern __shared__ char smem[];
    const uint32_t sb = smem_u32(smem);
    const int tid = threadIdx.x;
    const int l = tid & 31;
    const int wid = tid >> 5;
    const int warp_m = wid & 1;    // 2 x 64 rows
    const int warp_n = wid >> 1;   // 4 x 48 cols
    const int bm = blockIdx.y * BM;
    const int bn = blockIdx.x * BN;

    float acc[4][6][4];
#pragma unroll
    for (int mi = 0; mi < 4; mi++)
#pragma unroll
        for (int ni = 0; ni < 6; ni++)
#pragma unroll
            for (int q = 0; q < 4; q++) acc[mi][ni][q] = 0.0f;

    // cooperative load: 2560 16B chunks/stage, 10 per thread.
    // Region map (stage always within one KD-wide region):
    //   A terms: {hi, hi, lo};  B terms: {hi, lo, hi};  col = k0 % KD
    auto load_stage = [&](int s, int k0) {
        const int reg = k0 / KD;
        const int kk = k0 - reg * KD;
        const __nv_bfloat16* Abase = (reg == 2) ? Al : Ah;
        const __nv_bfloat16* Bbase = (reg == 1) ? Bl : Bh;
        uint32_t stage = sb + s * STAGE_B;
#pragma unroll
        for (int i = 0; i < 10; i++) {
            int id = tid + i * THREADS;
            int row = id >> 3;
            int c = id & 7;
            int cs = c ^ (row & 7);
            uint32_t dst = stage + row * 128 + cs * 16;
            const __nv_bfloat16* g;
            if (row < AROWS) g = Abase + (size_t)(bm + row) * KD + kk + c * 8;
            else             g = Bbase + (size_t)(bn + row - AROWS) * KD + kk + c * 8;
            cp_async16(dst, g);
        }
    };

    load_stage(0, 0);
    asm volatile("cp.async.commit_group;");
    load_stage(1, BK);
    asm volatile("cp.async.commit_group;");
    load_stage(2, 2 * BK);
    asm volatile("cp.async.commit_group;");

    // ldmatrix lane addressing within swizzled rows
    const int lr = l & 15;
    const int lc = l >> 4;
    const int lx = l & 7;

    for (int kt = 0; kt < NITER; kt++) {
        asm volatile("cp.async.wait_group 2;");
        __syncthreads();

        if (kt + 3 < NITER) load_stage((kt + 3) & 3, (kt + 3) * BK);
        asm volatile("cp.async.commit_group;");

        const uint32_t stage = sb + (kt & 3) * STAGE_B;
#pragma unroll
        for (int ksub = 0; ksub < 4; ksub++) {
            const int cs = (2 * ksub + lc) ^ lx;
            uint32_t a[4][4], b[3][4];
#pragma unroll
            for (int mi = 0; mi < 4; mi++) {
                int row = warp_m * 64 + mi * 16 + lr;
                ldsm4(a[mi], stage + row * 128 + cs * 16);
            }
#pragma unroll
            for (int q = 0; q < 3; q++) {
                int row = AROWS + warp_n * 48 + q * 16 + lr;
                ldsm4(b[q], stage + row * 128 + cs * 16);
            }
#pragma unroll
            for (int mi = 0; mi < 4; mi++)
#pragma unroll
                for (int q = 0; q < 3; q++) {
                    mma_bf16(acc[mi][2 * q],     a[mi], b[q][0], b[q][2]);
                    mma_bf16(acc[mi][2 * q + 1], a[mi], b[q][1], b[q][3]);
                }
        }
    }
    asm volatile("cp.async.wait_group 0;");
    __syncthreads();

    if (QUANTUM) {
        // stage accums through smem, then closed-form quantum head per 8-col group
        float* Cs = (float*)smem;
#pragma unroll
        for (int mi = 0; mi < 4; mi++)
#pragma unroll
            for (int ni = 0; ni < 6; ni++) {
                int row = warp_m * 64 + mi * 16 + (l >> 2);
                int col = warp_n * 48 + ni * 8 + (l & 3) * 2;
                *(float2*)&Cs[row * CPAD + col]       = make_float2(acc[mi][ni][0], acc[mi][ni][1]);
                *(float2*)&Cs[(row + 8) * CPAD + col] = make_float2(acc[mi][ni][2], acc[mi][ni][3]);
            }
        __syncthreads();

        float th[8];
#pragma unroll
        for (int j = 0; j < 8; j++) th[j] = theta[j];

        // 128 rows x 24 heads = 3072 tasks, 12 per thread
#pragma unroll
        for (int i = 0; i < 12; i++) {
            int g = tid + i * THREADS;
            int r = g / 24;
            int h = g - r * 24;
            int nn = bn + h * 8;
            const float* src = &Cs[r * CPAD + h * 8];
            float cc[8];
#pragma unroll
            for (int j = 0; j < 8; j++)
                cc[j] = cosf(src[j] + bias[nn + j] + th[j]);
            float o[8];
            float p = cc[0];
#pragma unroll
            for (int j = 1; j < 8; j++) { p *= cc[j]; o[j] = p; }
            float sp = cc[1];
#pragma unroll
            for (int j = 2; j < 8; j++) sp *= cc[j];
            o[0] = sp;
            uint32_t hi[4], lo[4];
#pragma unroll
            for (int q = 0; q < 4; q++) split_bf16x2(o[2 * q], o[2 * q + 1], hi[q], lo[q]);
            size_t base = (size_t)(bm + r) * KD + nn;
            *(uint4*)(Eh + base) = make_uint4(hi[0], hi[1], hi[2], hi[3]);
            *(uint4*)(El + base) = make_uint4(lo[0], lo[1], lo[2], lo[3]);
        }
    } else {
        // bias add + direct fp32 store
#pragma unroll
        for (int mi = 0; mi < 4; mi++)
#pragma unroll
            for (int ni = 0; ni < 6; ni++) {
                int row = bm + warp_m * 64 + mi * 16 + (l >> 2);
                int col = bn + warp_n * 48 + ni * 8 + (l & 3) * 2;
                float b0 = bias[col], b1 = bias[col + 1];
                *(float2*)&out[(size_t)row * N_DIM + col] =
                    make_float2(acc[mi][ni][0] + b0, acc[mi][ni][1] + b1);
                *(float2*)&out[(size_t)(row + 8) * N_DIM + col] =
                    make_float2(acc[mi][ni][2] + b0, acc[mi][ni][3] + b1);
            }
    }
}

extern "C" void kernel_launch(void* const* d_in, const int* in_sizes, int n_in,
                              void* d_out, int out_size)
{
    const float* x      = (const float*)d_in[0];
    const float* W_proj = (const float*)d_in[1];
    const float* b_proj = (const float*)d_in[2];
    const float* theta  = (const float*)d_in[3];
    const float* W_comb = (const float*)d_in[4];
    const float* b_comb = (const float*)d_in[5];
    float* out = (float*)d_out;

    cudaFuncSetAttribute(mma_gemm<true>,  cudaFuncAttributeMaxDynamicSharedMemorySize, SMEM_SZ);
    cudaFuncSetAttribute(mma_gemm<false>, cudaFuncAttributeMaxDynamicSharedMemorySize, SMEM_SZ);

    __nv_bfloat16 *Ah, *Al, *Bph, *Bpl, *Bch, *Bcl, *Eh, *El;
    cudaGetSymbolAddress((void**)&Ah,  g_Ah);
    cudaGetSymbolAddress((void**)&Al,  g_Al);
    cudaGetSymbolAddress((void**)&Bph, g_Bph);
    cudaGetSymbolAddress((void**)&Bpl, g_Bpl);
    cudaGetSymbolAddress((void**)&Bch, g_Bch);
    cudaGetSymbolAddress((void**)&Bcl, g_Bcl);
    cudaGetSymbolAddress((void**)&Eh,  g_Eh);
    cudaGetSymbolAddress((void**)&El,  g_El);

    const int total8 = M_DIM * KD / 8 + 2 * (N_DIM * KD / 8);
    split_kernel<<<(total8 + 255) / 256, 256>>>(x, W_proj, W_comb);

    dim3 grid(N_DIM / BN, M_DIM / BM);  // (4, 32) = 128 CTAs, single wave
    mma_gemm<true><<<grid, THREADS, SMEM_SZ>>>(Ah, Al, Bph, Bpl, b_proj, theta, Eh, El, nullptr);
    mma_gemm<false><<<grid, THREADS, SMEM_SZ>>>(Eh, El, Bch, Bcl, b_comb, nullptr, nullptr, nullptr, out);
}

// round 6
// speedup vs baseline: 3.2524x; 1.2216x over previous
#include <cuda_runtime.h>
#include <cuda_fp16.h>
#include <math.h>
#include <stdint.h>

// out = ((cos-product head)(x @ Wp^T + bp + theta)) @ Wc^T + bc
// Quantum head closed form (CNOT ring = linear XOR map on basis bits):
//   expz[w] = prod_{j=0..w} cos(ang_j)  (w>=1);  expz[0] = prod_{j=1..7} cos(ang_j)
//
// Tensor path: mma.sync m16n8k16 fp16 (HMMA; tcgen05 PTX rejected at sm_103 target).
// GEMM1 (x @ Wp^T): fp16 hi/lo 3-term split (K=2304) -> ~fp32-exact (dropped ~2^-24).
// GEMM2 (expz @ Wc^T): expz unsplit fp16, Wc hi/lo 2-term split (K=1536);
//   dominant error = fp16 truncation of expz (~2^-12 relative, norm-avg ~1e-4).

#define M_DIM 4096
#define N_DIM 768
#define KD    768
#define BM    128
#define BN    192
#define BK    64
#define THREADS 256
#define NSTAGE 4

#define AROWS   BM
#define TROWS   (BM + BN)      // 320 rows per stage (A then B)
#define STAGE_B (TROWS * 128)  // 40960 (swizzled 128B rows)
#define SMEM_SZ (NSTAGE * STAGE_B)   // 163840
#define CPAD    (BN + 4)

// ---- device scratch (allocation-free rule) ----
__device__ __half g_Ah[(size_t)M_DIM * KD], g_Al[(size_t)M_DIM * KD];
__device__ __half g_Bph[(size_t)N_DIM * KD], g_Bpl[(size_t)N_DIM * KD];
__device__ __half g_Bch[(size_t)N_DIM * KD], g_Bcl[(size_t)N_DIM * KD];
__device__ __half g_E[(size_t)M_DIM * KD];

// ---- helpers ----
__device__ __forceinline__ uint32_t smem_u32(const void* p) {
    uint32_t a;
    asm("{ .reg .u64 t; cvta.to.shared.u64 t, %1; cvt.u32.u64 %0, t; }" : "=r"(a) : "l"(p));
    return a;
}
__device__ __forceinline__ void cp_async16(uint32_t dst, const void* src) {
    asm volatile("cp.async.cg.shared.global [%0], [%1], 16;" :: "r"(dst), "l"(src));
}
__device__ __forceinline__ void ldsm4(uint32_t* r, uint32_t addr) {
    asm volatile("ldmatrix.sync.aligned.m8n8.x4.shared.b16 {%0,%1,%2,%3}, [%4];"
                 : "=r"(r[0]), "=r"(r[1]), "=r"(r[2]), "=r"(r[3]) : "r"(addr));
}
__device__ __forceinline__ void mma_f16(float* c, const uint32_t* a, uint32_t b0, uint32_t b1) {
    asm volatile(
        "mma.sync.aligned.m16n8k16.row.col.f32.f16.f16.f32 "
        "{%0,%1,%2,%3}, {%4,%5,%6,%7}, {%8,%9}, {%0,%1,%2,%3};"
        : "+f"(c[0]), "+f"(c[1]), "+f"(c[2]), "+f"(c[3])
        : "r"(a[0]), "r"(a[1]), "r"(a[2]), "r"(a[3]), "r"(b0), "r"(b1));
}
__device__ __forceinline__ void split_f16x2(float f0, float f1, uint32_t& hi, uint32_t& lo) {
    __half2 hh, ll;
    hh.x = __float2half_rn(f0);
    hh.y = __float2half_rn(f1);
    ll.x = __float2half_rn(f0 - __half2float(hh.x));
    ll.y = __float2half_rn(f1 - __half2float(hh.y));
    hi = *(uint32_t*)&hh;
    lo = *(uint32_t*)&ll;
}

// ---- fp32 -> fp16 hi/lo; 8 floats per thread, 16B stores ----
__global__ void split_kernel(const float* __restrict__ x,
                             const float* __restrict__ wp,
                             const float* __restrict__ wc) {
    const int n8x = M_DIM * KD / 8;
    const int n8w = N_DIM * KD / 8;
    int i = blockIdx.x * blockDim.x + threadIdx.x;
    const float* src; __half *hi, *lo; int j;
    if (i < n8x)              { src = x;  hi = g_Ah;  lo = g_Al;  j = i; }
    else if (i < n8x + n8w)   { src = wp; hi = g_Bph; lo = g_Bpl; j = i - n8x; }
    else if (i < n8x + 2*n8w) { src = wc; hi = g_Bch; lo = g_Bcl; j = i - n8x - n8w; }
    else return;
    float4 v0 = ((const float4*)src)[j * 2];
    float4 v1 = ((const float4*)src)[j * 2 + 1];
    uint32_t h[4], l[4];
    split_f16x2(v0.x, v0.y, h[0], l[0]);
    split_f16x2(v0.z, v0.w, h[1], l[1]);
    split_f16x2(v1.x, v1.y, h[2], l[2]);
    split_f16x2(v1.z, v1.w, h[3], l[3]);
    ((uint4*)hi)[j] = make_uint4(h[0], h[1], h[2], h[3]);
    ((uint4*)lo)[j] = make_uint4(l[0], l[1], l[2], l[3]);
}

// ---- GEMM: C[M,N](fp32) = sum over split-term regions of A @ B^T ----
// Region r (k0 = r*KD): A operand = (r==2) ? Al : Ah; B operand = (r==1) ? Bl : Bh.
//   GEMM1: NREG=3 -> Ah.Bh + Ah.Bl + Al.Bh ; GEMM2: NREG=2 -> A.Bh + A.Bl
// 128x192 CTA tile, 8 warps as 2x4 (64x48 warp tiles), BK=64, 4-stage cp.async,
// ONE __syncthreads per iter, XOR-swizzled 128B smem rows.
template <bool QUANTUM, int NREG>
__global__ __launch_bounds__(THREADS)
void mma_gemm(const __half* __restrict__ Ah, const __half* __restrict__ Al,
              const __half* __restrict__ Bh, const __half* __restrict__ Bl,
              const float* __restrict__ bias,
              const float* __restrict__ theta,
              __half* __restrict__ E,
              float* __restrict__ out)
{
    constexpr int NITER = NREG * KD / BK;
    extern __shared__ char smem[];
    const uint32_t sb = smem_u32(smem);
    const int tid = threadIdx.x;
    const int l = tid & 31;
    const int wid = tid >> 5;
    const int warp_m = wid & 1;    // 2 x 64 rows
    const int warp_n = wid >> 1;   // 4 x 48 cols
    const int bm = blockIdx.y * BM;
    const int bn = blockIdx.x * BN;

    float acc[4][6][4];
#pragma unroll
    for (int mi = 0; mi < 4; mi++)
#pragma unroll
        for (int ni = 0; ni < 6; ni++)
#pragma unroll
            for (int q = 0; q < 4; q++) acc[mi][ni][q] = 0.0f;

    // cooperative load: 2560 16B chunks/stage, 10 per thread
    auto load_stage = [&](int s, int k0) {
        const int reg = k0 / KD;
        const int kk = k0 - reg * KD;
        const __half* Abase = (reg == 2) ? Al : Ah;
        const __half* Bbase = (reg == 1) ? Bl : Bh;
        uint32_t stage = sb + s * STAGE_B;
#pragma unroll
        for (int i = 0; i < 10; i++) {
            int id = tid + i * THREADS;
            int row = id >> 3;
            int c = id & 7;
            int cs = c ^ (row & 7);
            uint32_t dst = stage + row * 128 + cs * 16;
            const __half* g;
            if (row < AROWS) g = Abase + (size_t)(bm + row) * KD + kk + c * 8;
            else             g = Bbase + (size_t)(bn + row - AROWS) * KD + kk + c * 8;
            cp_async16(dst, g);
        }
    };

    load_stage(0, 0);
    asm volatile("cp.async.commit_group;");
    load_stage(1, BK);
    asm volatile("cp.async.commit_group;");
    load_stage(2, 2 * BK);
    asm volatile("cp.async.commit_group;");

    // ldmatrix lane addressing within swizzled rows
    const int lr = l & 15;
    const int lc = l >> 4;
    const int lx = l & 7;

    for (int kt = 0; kt < NITER; kt++) {
        asm volatile("cp.async.wait_group 2;");
        __syncthreads();

        if (kt + 3 < NITER) load_stage((kt + 3) & 3, (kt + 3) * BK);
        asm volatile("cp.async.commit_group;");

        const uint32_t stage = sb + (kt & 3) * STAGE_B;
#pragma unroll
        for (int ksub = 0; ksub < 4; ksub++) {
            const int cs = (2 * ksub + lc) ^ lx;
            uint32_t a[4][4], b[3][4];
#pragma unroll
            for (int mi = 0; mi < 4; mi++) {
                int row = warp_m * 64 + mi * 16 + lr;
                ldsm4(a[mi], stage + row * 128 + cs * 16);
            }
#pragma unroll
            for (int q = 0; q < 3; q++) {
                int row = AROWS + warp_n * 48 + q * 16 + lr;
                ldsm4(b[q], stage + row * 128 + cs * 16);
            }
#pragma unroll
            for (int mi = 0; mi < 4; mi++)
#pragma unroll
                for (int q = 0; q < 3; q++) {
                    mma_f16(acc[mi][2 * q],     a[mi], b[q][0], b[q][2]);
                    mma_f16(acc[mi][2 * q + 1], a[mi], b[q][1], b[q][3]);
                }
        }
    }
    asm volatile("cp.async.wait_group 0;");
    __syncthreads();

    if (QUANTUM) {
        // stage accums through smem, then closed-form quantum head per 8-col group
        float* Cs = (float*)smem;
#pragma unroll
        for (int mi = 0; mi < 4; mi++)
#pragma unroll
            for (int ni = 0; ni < 6; ni++) {
                int row = warp_m * 64 + mi * 16 + (l >> 2);
                int col = warp_n * 48 + ni * 8 + (l & 3) * 2;
                *(float2*)&Cs[row * CPAD + col]       = make_float2(acc[mi][ni][0], acc[mi][ni][1]);
                *(float2*)&Cs[(row + 8) * CPAD + col] = make_float2(acc[mi][ni][2], acc[mi][ni][3]);
            }
        __syncthreads();

        float th[8];
#pragma unroll
        for (int j = 0; j < 8; j++) th[j] = theta[j];

        // 128 rows x 24 heads = 3072 tasks, 12 per thread
#pragma unroll
        for (int i = 0; i < 12; i++) {
            int g = tid + i * THREADS;
            int r = g / 24;
            int h = g - r * 24;
            int nn = bn + h * 8;
            const float* src = &Cs[r * CPAD + h * 8];
            float cc[8];
#pragma unroll
            for (int j = 0; j < 8; j++)
                cc[j] = cosf(src[j] + bias[nn + j] + th[j]);
            float o[8];
            float p = cc[0];
#pragma unroll
            for (int j = 1; j < 8; j++) { p *= cc[j]; o[j] = p; }
            float sp = cc[1];
#pragma unroll
            for (int j = 2; j < 8; j++) sp *= cc[j];
            o[0] = sp;
            uint32_t hv[4];
#pragma unroll
            for (int q = 0; q < 4; q++) {
                __half2 hh;
                hh.x = __float2half_rn(o[2 * q]);
                hh.y = __float2half_rn(o[2 * q + 1]);
                hv[q] = *(uint32_t*)&hh;
            }
            *(uint4*)(E + (size_t)(bm + r) * KD + nn) = make_uint4(hv[0], hv[1], hv[2], hv[3]);
        }
    } else {
        // bias add + direct fp32 store
#pragma unroll
        for (int mi = 0; mi < 4; mi++)
#pragma unroll
            for (int ni = 0; ni < 6; ni++) {
                int row = bm + warp_m * 64 + mi * 16 + (l >> 2);
                int col = bn + warp_n * 48 + ni * 8 + (l & 3) * 2;
                float b0 = bias[col], b1 = bias[col + 1];
                *(float2*)&out[(size_t)row * N_DIM + col] =
                    make_float2(acc[mi][ni][0] + b0, acc[mi][ni][1] + b1);
                *(float2*)&out[(size_t)(row + 8) * N_DIM + col] =
                    make_float2(acc[mi][ni][2] + b0, acc[mi][ni][3] + b1);
            }
    }
}

extern "C" void kernel_launch(void* const* d_in, const int* in_sizes, int n_in,
                              void* d_out, int out_size)
{
    const float* x      = (const float*)d_in[0];
    const float* W_proj = (const float*)d_in[1];
    const float* b_proj = (const float*)d_in[2];
    const float* theta  = (const float*)d_in[3];
    const float* W_comb = (const float*)d_in[4];
    const float* b_comb = (const float*)d_in[5];
    float* out = (float*)d_out;

    cudaFuncSetAttribute(mma_gemm<true, 3>,  cudaFuncAttributeMaxDynamicSharedMemorySize, SMEM_SZ);
    cudaFuncSetAttribute(mma_gemm<false, 2>, cudaFuncAttributeMaxDynamicSharedMemorySize, SMEM_SZ);

    __half *Ah, *Al, *Bph, *Bpl, *Bch, *Bcl, *E;
    cudaGetSymbolAddress((void**)&Ah,  g_Ah);
    cudaGetSymbolAddress((void**)&Al,  g_Al);
    cudaGetSymbolAddress((void**)&Bph, g_Bph);
    cudaGetSymbolAddress((void**)&Bpl, g_Bpl);
    cudaGetSymbolAddress((void**)&Bch, g_Bch);
    cudaGetSymbolAddress((void**)&Bcl, g_Bcl);
    cudaGetSymbolAddress((void**)&E,   g_E);

    const int total8 = M_DIM * KD / 8 + 2 * (N_DIM * KD / 8);
    split_kernel<<<(total8 + 255) / 256, 256>>>(x, W_proj, W_comb);

    dim3 grid(N_DIM / BN, M_DIM / BM);  // (4, 32) = 128 CTAs, single wave
    mma_gemm<true, 3><<<grid, THREADS, SMEM_SZ>>>(Ah, Al, Bph, Bpl, b_proj, theta, E, nullptr);
    mma_gemm<false, 2><<<grid, THREADS, SMEM_SZ>>>(E, nullptr, Bch, Bcl, b_comb, nullptr, nullptr, out);
}

// round 8
// speedup vs baseline: 3.8171x; 1.1736x over previous
#include <cuda_runtime.h>
#include <cuda_fp16.h>
#include <math.h>
#include <stdint.h>

// out = ((cos-product head)(x @ Wp^T + bp + theta)) @ Wc^T + bc
// Quantum head closed form (CNOT ring = linear XOR map on basis bits):
//   expz[w] = prod_{j=0..w} cos(ang_j)  (w>=1);  expz[0] = prod_{j=1..7} cos(ang_j)
//
// Tensor path: mma.sync m16n8k16 fp16 (HMMA; tcgen05 PTX rejected at sm_103 target).
// GEMM1 (x @ Wp^T): fp16 hi/lo 3-term split (K=2304) -> ~fp32-exact.
// GEMM2 (expz @ Wc^T): plain fp16 1-term (K=768); error budget:
//   expz fp16 trunc ~1.9e-4 (measured) + Wc fp16 trunc ~1.4e-4 (model) << 1e-3.

#define M_DIM 4096
#define N_DIM 768
#define KD    768
#define BM    128
#define BN    192
#define BK    64
#define THREADS 256
#define NSTAGE 4

#define AROWS   BM
#define TROWS   (BM + BN)      // 320 rows per stage (A then B)
#define STAGE_B (TROWS * 128)  // 40960 (swizzled 128B rows)
#define SMEM_SZ (NSTAGE * STAGE_B)   // 163840
#define CPAD    (BN + 4)

// ---- device scratch (allocation-free rule) ----
__device__ __half g_Ah[(size_t)M_DIM * KD], g_Al[(size_t)M_DIM * KD];
__device__ __half g_Bph[(size_t)N_DIM * KD], g_Bpl[(size_t)N_DIM * KD];
__device__ __half g_Bc[(size_t)N_DIM * KD];
__device__ __half g_E[(size_t)M_DIM * KD];

// ---- helpers ----
__device__ __forceinline__ uint32_t smem_u32(const void* p) {
    uint32_t a;
    asm("{ .reg .u64 t; cvta.to.shared.u64 t, %1; cvt.u32.u64 %0, t; }" : "=r"(a) : "l"(p));
    return a;
}
__device__ __forceinline__ void cp_async16(uint32_t dst, const void* src) {
    asm volatile("cp.async.cg.shared.global [%0], [%1], 16;" :: "r"(dst), "l"(src));
}
__device__ __forceinline__ void ldsm4(uint32_t* r, uint32_t addr) {
    asm volatile("ldmatrix.sync.aligned.m8n8.x4.shared.b16 {%0,%1,%2,%3}, [%4];"
                 : "=r"(r[0]), "=r"(r[1]), "=r"(r[2]), "=r"(r[3]) : "r"(addr));
}
__device__ __forceinline__ void mma_f16(float* c, const uint32_t* a, uint32_t b0, uint32_t b1) {
    asm volatile(
        "mma.sync.aligned.m16n8k16.row.col.f32.f16.f16.f32 "
        "{%0,%1,%2,%3}, {%4,%5,%6,%7}, {%8,%9}, {%0,%1,%2,%3};"
        : "+f"(c[0]), "+f"(c[1]), "+f"(c[2]), "+f"(c[3])
        : "r"(a[0]), "r"(a[1]), "r"(a[2]), "r"(a[3]), "r"(b0), "r"(b1));
}
__device__ __forceinline__ void split_f16x2(float f0, float f1, uint32_t& hi, uint32_t& lo) {
    __half2 hh, ll;
    hh.x = __float2half_rn(f0);
    hh.y = __float2half_rn(f1);
    ll.x = __float2half_rn(f0 - __half2float(hh.x));
    ll.y = __float2half_rn(f1 - __half2float(hh.y));
    hi = *(uint32_t*)&hh;
    lo = *(uint32_t*)&ll;
}

// ---- fp32 -> fp16 hi/lo (lo==nullptr -> convert only); 8 floats/thread ----
__global__ void split_kernel(const float* __restrict__ x,
                             const float* __restrict__ wp,
                             const float* __restrict__ wc) {
    const int n8x = M_DIM * KD / 8;
    const int n8w = N_DIM * KD / 8;
    int i = blockIdx.x * blockDim.x + threadIdx.x;
    const float* src; __half *hi, *lo; int j;
    if (i < n8x)              { src = x;  hi = g_Ah;  lo = g_Al;  j = i; }
    else if (i < n8x + n8w)   { src = wp; hi = g_Bph; lo = g_Bpl; j = i - n8x; }
    else if (i < n8x + 2*n8w) { src = wc; hi = g_Bc;  lo = nullptr; j = i - n8x - n8w; }
    else return;
    float4 v0 = ((const float4*)src)[j * 2];
    float4 v1 = ((const float4*)src)[j * 2 + 1];
    uint32_t h[4], l[4];
    split_f16x2(v0.x, v0.y, h[0], l[0]);
    split_f16x2(v0.z, v0.w, h[1], l[1]);
    split_f16x2(v1.x, v1.y, h[2], l[2]);
    split_f16x2(v1.z, v1.w, h[3], l[3]);
    ((uint4*)hi)[j] = make_uint4(h[0], h[1], h[2], h[3]);
    if (lo) ((uint4*)lo)[j] = make_uint4(l[0], l[1], l[2], l[3]);
}

// ---- GEMM: C[M,N](fp32) = sum over split-term regions of A @ B^T ----
// Region r (k0 = r*KD): A operand = (r==2) ? Al : Ah; B operand = (r==1) ? Bl : Bh.
//   GEMM1: NREG=3 -> Ah.Bh + Ah.Bl + Al.Bh ; GEMM2: NREG=1 -> A.B
// 128x192 CTA tile, 8 warps as 2x4 (64x48 warp tiles), BK=64, 4-stage cp.async,
// ONE __syncthreads per iter, XOR-swizzled 128B smem rows.
template <bool QUANTUM, int NREG>
__global__ __launch_bounds__(THREADS)
void mma_gemm(const __half* __restrict__ Ah, const __half* __restrict__ Al,
              const __half* __restrict__ Bh, const __half* __restrict__ Bl,
              const float* __restrict__ bias,
              const float* __restrict__ theta,
              __half* __restrict__ E,
              float* __restrict__ out)
{
    constexpr int NITER = NREG * KD / BK;
    extern __shared__ char smem[];
    const uint32_t sb = smem_u32(smem);
    const int tid = threadIdx.x;
    const int l = tid & 31;
    const int wid = tid >> 5;
    const int warp_m = wid & 1;    // 2 x 64 rows
    const int warp_n = wid >> 1;   // 4 x 48 cols
    const int bm = blockIdx.y * BM;
    const int bn = blockIdx.x * BN;

    float acc[4][6][4];
#pragma unroll
    for (int mi = 0; mi < 4; mi++)
#pragma unroll
        for (int ni = 0; ni < 6; ni++)
#pragma unroll
            for (int q = 0; q < 4; q++) acc[mi][ni][q] = 0.0f;

    // cooperative load: 2560 16B chunks/stage, 10 per thread
    auto load_stage = [&](int s, int k0) {
        const int reg = k0 / KD;
        const int kk = k0 - reg * KD;
        const __half* Abase = (reg == 2) ? Al : Ah;
        const __half* Bbase = (reg == 1) ? Bl : Bh;
        uint32_t stage = sb + s * STAGE_B;
#pragma unroll
        for (int i = 0; i < 10; i++) {
            int id = tid + i * THREADS;
            int row = id >> 3;
            int c = id & 7;
            int cs = c ^ (row & 7);
            uint32_t dst = stage + row * 128 + cs * 16;
            const __half* g;
            if (row < AROWS) g = Abase + (size_t)(bm + row) * KD + kk + c * 8;
            else             g = Bbase + (size_t)(bn + row - AROWS) * KD + kk + c * 8;
            cp_async16(dst, g);
        }
    };

    load_stage(0, 0);
    asm volatile("cp.async.commit_group;");
    load_stage(1, BK);
    asm volatile("cp.async.commit_group;");
    load_stage(2, 2 * BK);
    asm volatile("cp.async.commit_group;");

    // ldmatrix lane addressing within swizzled rows
    const int lr = l & 15;
    const int lc = l >> 4;
    const int lx = l & 7;

    for (int kt = 0; kt < NITER; kt++) {
        asm volatile("cp.async.wait_group 2;");
        __syncthreads();

        if (kt + 3 < NITER) load_stage((kt + 3) & 3, (kt + 3) * BK);
        asm volatile("cp.async.commit_group;");

        const uint32_t stage = sb + (kt & 3) * STAGE_B;
#pragma unroll
        for (int ksub = 0; ksub < 4; ksub++) {
            const int cs = (2 * ksub + lc) ^ lx;
            uint32_t a[4][4], b[3][4];
#pragma unroll
            for (int mi = 0; mi < 4; mi++) {
                int row = warp_m * 64 + mi * 16 + lr;
                ldsm4(a[mi], stage + row * 128 + cs * 16);
            }
#pragma unroll
            for (int q = 0; q < 3; q++) {
                int row = AROWS + warp_n * 48 + q * 16 + lr;
                ldsm4(b[q], stage + row * 128 + cs * 16);
            }
#pragma unroll
            for (int mi = 0; mi < 4; mi++)
#pragma unroll
                for (int q = 0; q < 3; q++) {
                    mma_f16(acc[mi][2 * q],     a[mi], b[q][0], b[q][2]);
                    mma_f16(acc[mi][2 * q + 1], a[mi], b[q][1], b[q][3]);
                }
        }
    }
    asm volatile("cp.async.wait_group 0;");
    __syncthreads();

    if (QUANTUM) {
        // stage accums through smem, then closed-form quantum head per 8-col group
        float* Cs = (float*)smem;
#pragma unroll
        for (int mi = 0; mi < 4; mi++)
#pragma unroll
            for (int ni = 0; ni < 6; ni++) {
                int row = warp_m * 64 + mi * 16 + (l >> 2);
                int col = warp_n * 48 + ni * 8 + (l & 3) * 2;
                *(float2*)&Cs[row * CPAD + col]       = make_float2(acc[mi][ni][0], acc[mi][ni][1]);
                *(float2*)&Cs[(row + 8) * CPAD + col] = make_float2(acc[mi][ni][2], acc[mi][ni][3]);
            }
        __syncthreads();

        float th[8];
#pragma unroll
        for (int j = 0; j < 8; j++) th[j] = theta[j];

        // 128 rows x 24 heads = 3072 tasks, 12 per thread
#pragma unroll
        for (int i = 0; i < 12; i++) {
            int g = tid + i * THREADS;
            int r = g / 24;
            int h = g - r * 24;
            int nn = bn + h * 8;
            const float* src = &Cs[r * CPAD + h * 8];
            float cc[8];
#pragma unroll
            for (int j = 0; j < 8; j++)
                cc[j] = cosf(src[j] + bias[nn + j] + th[j]);
            float o[8];
            float p = cc[0];
#pragma unroll
            for (int j = 1; j < 8; j++) { p *= cc[j]; o[j] = p; }
            float sp = cc[1];
#pragma unroll
            for (int j = 2; j < 8; j++) sp *= cc[j];
            o[0] = sp;
            uint32_t hv[4];
#pragma unroll
            for (int q = 0; q < 4; q++) {
                __half2 hh;
                hh.x = __float2half_rn(o[2 * q]);
                hh.y = __float2half_rn(o[2 * q + 1]);
                hv[q] = *(uint32_t*)&hh;
            }
            *(uint4*)(E + (size_t)(bm + r) * KD + nn) = make_uint4(hv[0], hv[1], hv[2], hv[3]);
        }
    } else {
        // bias add + direct fp32 store
#pragma unroll
        for (int mi = 0; mi < 4; mi++)
#pragma unroll
            for (int ni = 0; ni < 6; ni++) {
                int row = bm + warp_m * 64 + mi * 16 + (l >> 2);
                int col = bn + warp_n * 48 + ni * 8 + (l & 3) * 2;
                float b0 = bias[col], b1 = bias[col + 1];
                *(float2*)&out[(size_t)row * N_DIM + col] =
                    make_float2(acc[mi][ni][0] + b0, acc[mi][ni][1] + b1);
                *(float2*)&out[(size_t)(row + 8) * N_DIM + col] =
                    make_float2(acc[mi][ni][2] + b0, acc[mi][ni][3] + b1);
            }
    }
}

extern "C" void kernel_launch(void* const* d_in, const int* in_sizes, int n_in,
                              void* d_out, int out_size)
{
    const float* x      = (const float*)d_in[0];
    const float* W_proj = (const float*)d_in[1];
    const float* b_proj = (const float*)d_in[2];
    const float* theta  = (const float*)d_in[3];
    const float* W_comb = (const float*)d_in[4];
    const float* b_comb = (const float*)d_in[5];
    float* out = (float*)d_out;

    cudaFuncSetAttribute(mma_gemm<true, 3>,  cudaFuncAttributeMaxDynamicSharedMemorySize, SMEM_SZ);
    cudaFuncSetAttribute(mma_gemm<false, 1>, cudaFuncAttributeMaxDynamicSharedMemorySize, SMEM_SZ);

    __half *Ah, *Al, *Bph, *Bpl, *Bc, *E;
    cudaGetSymbolAddress((void**)&Ah,  g_Ah);
    cudaGetSymbolAddress((void**)&Al,  g_Al);
    cudaGetSymbolAddress((void**)&Bph, g_Bph);
    cudaGetSymbolAddress((void**)&Bpl, g_Bpl);
    cudaGetSymbolAddress((void**)&Bc,  g_Bc);
    cudaGetSymbolAddress((void**)&E,   g_E);

    const int total8 = M_DIM * KD / 8 + 2 * (N_DIM * KD / 8);
    split_kernel<<<(total8 + 255) / 256, 256>>>(x, W_proj, W_comb);

    dim3 grid(N_DIM / BN, M_DIM / BM);  // (4, 32) = 128 CTAs, single wave
    mma_gemm<true, 3><<<grid, THREADS, SMEM_SZ>>>(Ah, Al, Bph, Bpl, b_proj, theta, E, nullptr);
    mma_gemm<false, 1><<<grid, THREADS, SMEM_SZ>>>(E, nullptr, Bc, nullptr, b_comb, nullptr, nullptr, out);
}

// round 9
// speedup vs baseline: 4.6306x; 1.2131x over previous
#include <cuda_runtime.h>
#include <cuda_fp16.h>
#include <math.h>
#include <stdint.h>

// out = ((cos-product head)(x @ Wp^T + bp + theta)) @ Wc^T + bc
// Quantum head closed form (CNOT ring = linear XOR map on basis bits):
//   expz[w] = prod_{j=0..w} cos(ang_j)  (w>=1);  expz[0] = prod_{j=1..7} cos(ang_j)
//
// Tensor path: mma.sync m16n8k16 fp16 (HMMA; tcgen05 PTX rejected at sm_103 target).
// GEMM1 (x @ Wp^T): x as fp16 hi/lo 2-term (K=1536), Wp plain fp16.
//   err: dropped x.wp_lo ~2.4e-4 rad angle noise -> ~4.2e-4 out contribution.
// GEMM2 (expz @ Wc^T): plain fp16 1-term (K=768); expz+Wc trunc ~2.8e-4 (measured).
// Combined ~5e-4 << 1e-3 gate.

#define M_DIM 4096
#define N_DIM 768
#define KD    768
#define BM    128
#define BN    192
#define BK    64
#define THREADS 256
#define NSTAGE 4

#define AROWS   BM
#define TROWS   (BM + BN)      // 320 rows per stage (A then B)
#define STAGE_B (TROWS * 128)  // 40960 (swizzled 128B rows)
#define SMEM_SZ (NSTAGE * STAGE_B)   // 163840
#define CPAD    (BN + 4)

// ---- device scratch (allocation-free rule) ----
__device__ __half g_Ah[(size_t)M_DIM * KD], g_Al[(size_t)M_DIM * KD];
__device__ __half g_Bp[(size_t)N_DIM * KD];
__device__ __half g_Bc[(size_t)N_DIM * KD];
__device__ __half g_E[(size_t)M_DIM * KD];

// ---- helpers ----
__device__ __forceinline__ uint32_t smem_u32(const void* p) {
    uint32_t a;
    asm("{ .reg .u64 t; cvta.to.shared.u64 t, %1; cvt.u32.u64 %0, t; }" : "=r"(a) : "l"(p));
    return a;
}
__device__ __forceinline__ void cp_async16(uint32_t dst, const void* src) {
    asm volatile("cp.async.cg.shared.global [%0], [%1], 16;" :: "r"(dst), "l"(src));
}
__device__ __forceinline__ void ldsm4(uint32_t* r, uint32_t addr) {
    asm volatile("ldmatrix.sync.aligned.m8n8.x4.shared.b16 {%0,%1,%2,%3}, [%4];"
                 : "=r"(r[0]), "=r"(r[1]), "=r"(r[2]), "=r"(r[3]) : "r"(addr));
}
__device__ __forceinline__ void mma_f16(float* c, const uint32_t* a, uint32_t b0, uint32_t b1) {
    asm volatile(
        "mma.sync.aligned.m16n8k16.row.col.f32.f16.f16.f32 "
        "{%0,%1,%2,%3}, {%4,%5,%6,%7}, {%8,%9}, {%0,%1,%2,%3};"
        : "+f"(c[0]), "+f"(c[1]), "+f"(c[2]), "+f"(c[3])
        : "r"(a[0]), "r"(a[1]), "r"(a[2]), "r"(a[3]), "r"(b0), "r"(b1));
}
__device__ __forceinline__ void split_f16x2(float f0, float f1, uint32_t& hi, uint32_t& lo) {
    __half2 hh, ll;
    hh.x = __float2half_rn(f0);
    hh.y = __float2half_rn(f1);
    ll.x = __float2half_rn(f0 - __half2float(hh.x));
    ll.y = __float2half_rn(f1 - __half2float(hh.y));
    hi = *(uint32_t*)&hh;
    lo = *(uint32_t*)&ll;
}

// ---- fp32 -> fp16 hi(/lo for x only); 8 floats per thread, 16B stores ----
__global__ void split_kernel(const float* __restrict__ x,
                             const float* __restrict__ wp,
                             const float* __restrict__ wc) {
    const int n8x = M_DIM * KD / 8;
    const int n8w = N_DIM * KD / 8;
    int i = blockIdx.x * blockDim.x + threadIdx.x;
    const float* src; __half *hi, *lo; int j;
    if (i < n8x)              { src = x;  hi = g_Ah; lo = g_Al;   j = i; }
    else if (i < n8x + n8w)   { src = wp; hi = g_Bp; lo = nullptr; j = i - n8x; }
    else if (i < n8x + 2*n8w) { src = wc; hi = g_Bc; lo = nullptr; j = i - n8x - n8w; }
    else return;
    float4 v0 = ((const float4*)src)[j * 2];
    float4 v1 = ((const float4*)src)[j * 2 + 1];
    uint32_t h[4], l[4];
    split_f16x2(v0.x, v0.y, h[0], l[0]);
    split_f16x2(v0.z, v0.w, h[1], l[1]);
    split_f16x2(v1.x, v1.y, h[2], l[2]);
    split_f16x2(v1.z, v1.w, h[3], l[3]);
    ((uint4*)hi)[j] = make_uint4(h[0], h[1], h[2], h[3]);
    if (lo) ((uint4*)lo)[j] = make_uint4(l[0], l[1], l[2], l[3]);
}

// ---- GEMM: C[M,N](fp32) = sum over split-term regions of A @ B^T ----
// Region r (k0 = r*KD): A operand = (r==1) ? Al : Ah; B operand = Bh always.
//   GEMM1: NREG=2 -> (Ah + Al) @ Bh ; GEMM2: NREG=1 -> A @ B
// 128x192 CTA tile, 8 warps as 2x4 (64x48 warp tiles), BK=64, 4-stage cp.async,
// ONE __syncthreads per iter, XOR-swizzled 128B smem rows.
template <bool QUANTUM, int NREG>
__global__ __launch_bounds__(THREADS)
void mma_gemm(const __half* __restrict__ Ah, const __half* __restrict__ Al,
              const __half* __restrict__ Bh,
              const float* __restrict__ bias,
              const float* __restrict__ theta,
              __half* __restrict__ E,
              float* __restrict__ out)
{
    constexpr int NITER = NREG * KD / BK;
    extern __shared__ char smem[];
    const uint32_t sb = smem_u32(smem);
    const int tid = threadIdx.x;
    const int l = tid & 31;
    const int wid = tid >> 5;
    const int warp_m = wid & 1;    // 2 x 64 rows
    const int warp_n = wid >> 1;   // 4 x 48 cols
    const int bm = blockIdx.y * BM;
    const int bn = blockIdx.x * BN;

    float acc[4][6][4];
#pragma unroll
    for (int mi = 0; mi < 4; mi++)
#pragma unroll
        for (int ni = 0; ni < 6; ni++)
#pragma unroll
            for (int q = 0; q < 4; q++) acc[mi][ni][q] = 0.0f;

    // cooperative load: 2560 16B chunks/stage, 10 per thread
    auto load_stage = [&](int s, int k0) {
        const int reg = k0 / KD;
        const int kk = k0 - reg * KD;
        const __half* Abase = (reg == 1) ? Al : Ah;
        uint32_t stage = sb + s * STAGE_B;
#pragma unroll
        for (int i = 0; i < 10; i++) {
            int id = tid + i * THREADS;
            int row = id >> 3;
            int c = id & 7;
            int cs = c ^ (row & 7);
            uint32_t dst = stage + row * 128 + cs * 16;
            const __half* g;
            if (row < AROWS) g = Abase + (size_t)(bm + row) * KD + kk + c * 8;
            else             g = Bh + (size_t)(bn + row - AROWS) * KD + kk + c * 8;
            cp_async16(dst, g);
        }
    };

    load_stage(0, 0);
    asm volatile("cp.async.commit_group;");
    load_stage(1, BK);
    asm volatile("cp.async.commit_group;");
    load_stage(2, 2 * BK);
    asm volatile("cp.async.commit_group;");

    // ldmatrix lane addressing within swizzled rows
    const int lr = l & 15;
    const int lc = l >> 4;
    const int lx = l & 7;

    for (int kt = 0; kt < NITER; kt++) {
        asm volatile("cp.async.wait_group 2;");
        __syncthreads();

        if (kt + 3 < NITER) load_stage((kt + 3) & 3, (kt + 3) * BK);
        asm volatile("cp.async.commit_group;");

        const uint32_t stage = sb + (kt & 3) * STAGE_B;
#pragma unroll
        for (int ksub = 0; ksub < 4; ksub++) {
            const int cs = (2 * ksub + lc) ^ lx;
            uint32_t a[4][4], b[3][4];
#pragma unroll
            for (int mi = 0; mi < 4; mi++) {
                int row = warp_m * 64 + mi * 16 + lr;
                ldsm4(a[mi], stage + row * 128 + cs * 16);
            }
#pragma unroll
            for (int q = 0; q < 3; q++) {
                int row = AROWS + warp_n * 48 + q * 16 + lr;
                ldsm4(b[q], stage + row * 128 + cs * 16);
            }
#pragma unroll
            for (int mi = 0; mi < 4; mi++)
#pragma unroll
                for (int q = 0; q < 3; q++) {
                    mma_f16(acc[mi][2 * q],     a[mi], b[q][0], b[q][2]);
                    mma_f16(acc[mi][2 * q + 1], a[mi], b[q][1], b[q][3]);
                }
        }
    }
    asm volatile("cp.async.wait_group 0;");
    __syncthreads();

    if (QUANTUM) {
        // stage accums through smem, then closed-form quantum head per 8-col group
        float* Cs = (float*)smem;
#pragma unroll
        for (int mi = 0; mi < 4; mi++)
#pragma unroll
            for (int ni = 0; ni < 6; ni++) {
                int row = warp_m * 64 + mi * 16 + (l >> 2);
                int col = warp_n * 48 + ni * 8 + (l & 3) * 2;
                *(float2*)&Cs[row * CPAD + col]       = make_float2(acc[mi][ni][0], acc[mi][ni][1]);
                *(float2*)&Cs[(row + 8) * CPAD + col] = make_float2(acc[mi][ni][2], acc[mi][ni][3]);
            }
        __syncthreads();

        float th[8];
#pragma unroll
        for (int j = 0; j < 8; j++) th[j] = theta[j];

        // 128 rows x 24 heads = 3072 tasks, 12 per thread
#pragma unroll
        for (int i = 0; i < 12; i++) {
            int g = tid + i * THREADS;
            int r = g / 24;
            int h = g - r * 24;
            int nn = bn + h * 8;
            const float* src = &Cs[r * CPAD + h * 8];
            float cc[8];
#pragma unroll
            for (int j = 0; j < 8; j++)
                cc[j] = cosf(src[j] + bias[nn + j] + th[j]);
            float o[8];
            float p = cc[0];
#pragma unroll
            for (int j = 1; j < 8; j++) { p *= cc[j]; o[j] = p; }
            float sp = cc[1];
#pragma unroll
            for (int j = 2; j < 8; j++) sp *= cc[j];
            o[0] = sp;
            uint32_t hv[4];
#pragma unroll
            for (int q = 0; q < 4; q++) {
                __half2 hh;
                hh.x = __float2half_rn(o[2 * q]);
                hh.y = __float2half_rn(o[2 * q + 1]);
                hv[q] = *(uint32_t*)&hh;
            }
            *(uint4*)(E + (size_t)(bm + r) * KD + nn) = make_uint4(hv[0], hv[1], hv[2], hv[3]);
        }
    } else {
        // bias add + direct fp32 store
#pragma unroll
        for (int mi = 0; mi < 4; mi++)
#pragma unroll
            for (int ni = 0; ni < 6; ni++) {
                int row = bm + warp_m * 64 + mi * 16 + (l >> 2);
                int col = bn + warp_n * 48 + ni * 8 + (l & 3) * 2;
                float b0 = bias[col], b1 = bias[col + 1];
                *(float2*)&out[(size_t)row * N_DIM + col] =
                    make_float2(acc[mi][ni][0] + b0, acc[mi][ni][1] + b1);
                *(float2*)&out[(size_t)(row + 8) * N_DIM + col] =
                    make_float2(acc[mi][ni][2] + b0, acc[mi][ni][3] + b1);
            }
    }
}

extern "C" void kernel_launch(void* const* d_in, const int* in_sizes, int n_in,
                              void* d_out, int out_size)
{
    const float* x      = (const float*)d_in[0];
    const float* W_proj = (const float*)d_in[1];
    const float* b_proj = (const float*)d_in[2];
    const float* theta  = (const float*)d_in[3];
    const float* W_comb = (const float*)d_in[4];
    const float* b_comb = (const float*)d_in[5];
    float* out = (float*)d_out;

    cudaFuncSetAttribute(mma_gemm<true, 2>,  cudaFuncAttributeMaxDynamicSharedMemorySize, SMEM_SZ);
    cudaFuncSetAttribute(mma_gemm<false, 1>, cudaFuncAttributeMaxDynamicSharedMemorySize, SMEM_SZ);

    __half *Ah, *Al, *Bp, *Bc, *E;
    cudaGetSymbolAddress((void**)&Ah, g_Ah);
    cudaGetSymbolAddress((void**)&Al, g_Al);
    cudaGetSymbolAddress((void**)&Bp, g_Bp);
    cudaGetSymbolAddress((void**)&Bc, g_Bc);
    cudaGetSymbolAddress((void**)&E,  g_E);

    const int total8 = M_DIM * KD / 8 + 2 * (N_DIM * KD / 8);
    split_kernel<<<(total8 + 255) / 256, 256>>>(x, W_proj, W_comb);

    dim3 grid(N_DIM / BN, M_DIM / BM);  // (4, 32) = 128 CTAs, single wave
    mma_gemm<true, 2><<<grid, THREADS, SMEM_SZ>>>(Ah, Al, Bp, b_proj, theta, E, nullptr);
    mma_gemm<false, 1><<<grid, THREADS, SMEM_SZ>>>(E, nullptr, Bc, b_comb, nullptr, nullptr, out);
}

// round 10
// speedup vs baseline: 5.7001x; 1.2310x over previous
#include <cuda_runtime.h>
#include <cuda_fp16.h>
#include <math.h>
#include <stdint.h>

// out = ((cos-product head)(x @ Wp^T + bp + theta)) @ Wc^T + bc
// Quantum head closed form (CNOT ring = linear XOR map on basis bits):
//   expz[w] = prod_{j=0..w} cos(ang_j)  (w>=1);  expz[0] = prod_{j=1..7} cos(ang_j)
//
// Tensor path: mma.sync m16n8k16 fp16 (HMMA; tcgen05 PTX rejected at sm_103 target).
// Both GEMMs plain fp16 (K=768), fp32 accumulate.
// Error ledger (measured R6/R8/R9 + model): expz trunc 1.9e-4, Wc trunc 2.1e-4,
// Wp trunc 3.5e-4, x trunc ~3.5e-4 -> combined ~5.7e-4 < 1e-3 gate.

#define M_DIM 4096
#define N_DIM 768
#define KD    768
#define BM    128
#define BN    192
#define BK    64
#define NITER (KD / BK)        // 12
#define THREADS 256
#define NSTAGE 4

#define AROWS   BM
#define TROWS   (BM + BN)      // 320 rows per stage (A then B)
#define STAGE_B (TROWS * 128)  // 40960 (swizzled 128B rows)
#define SMEM_SZ (NSTAGE * STAGE_B)   // 163840
#define CPAD    (BN + 4)

// ---- device scratch (allocation-free rule) ----
__device__ __half g_A[(size_t)M_DIM * KD];
__device__ __half g_Bp[(size_t)N_DIM * KD];
__device__ __half g_Bc[(size_t)N_DIM * KD];
__device__ __half g_E[(size_t)M_DIM * KD];

// ---- helpers ----
__device__ __forceinline__ uint32_t smem_u32(const void* p) {
    uint32_t a;
    asm("{ .reg .u64 t; cvta.to.shared.u64 t, %1; cvt.u32.u64 %0, t; }" : "=r"(a) : "l"(p));
    return a;
}
__device__ __forceinline__ void cp_async16(uint32_t dst, const void* src) {
    asm volatile("cp.async.cg.shared.global [%0], [%1], 16;" :: "r"(dst), "l"(src));
}
__device__ __forceinline__ void ldsm4(uint32_t* r, uint32_t addr) {
    asm volatile("ldmatrix.sync.aligned.m8n8.x4.shared.b16 {%0,%1,%2,%3}, [%4];"
                 : "=r"(r[0]), "=r"(r[1]), "=r"(r[2]), "=r"(r[3]) : "r"(addr));
}
__device__ __forceinline__ void mma_f16(float* c, const uint32_t* a, uint32_t b0, uint32_t b1) {
    asm volatile(
        "mma.sync.aligned.m16n8k16.row.col.f32.f16.f16.f32 "
        "{%0,%1,%2,%3}, {%4,%5,%6,%7}, {%8,%9}, {%0,%1,%2,%3};"
        : "+f"(c[0]), "+f"(c[1]), "+f"(c[2]), "+f"(c[3])
        : "r"(a[0]), "r"(a[1]), "r"(a[2]), "r"(a[3]), "r"(b0), "r"(b1));
}

// ---- fp32 -> fp16 convert; 8 floats per thread, 16B stores ----
__global__ void conv_kernel(const float* __restrict__ x,
                            const float* __restrict__ wp,
                            const float* __restrict__ wc) {
    const int n8x = M_DIM * KD / 8;
    const int n8w = N_DIM * KD / 8;
    int i = blockIdx.x * blockDim.x + threadIdx.x;
    const float* src; __half* dst; int j;
    if (i < n8x)              { src = x;  dst = g_A;  j = i; }
    else if (i < n8x + n8w)   { src = wp; dst = g_Bp; j = i - n8x; }
    else if (i < n8x + 2*n8w) { src = wc; dst = g_Bc; j = i - n8x - n8w; }
    else return;
    float4 v0 = ((const float4*)src)[j * 2];
    float4 v1 = ((const float4*)src)[j * 2 + 1];
    __half2 h0 = __floats2half2_rn(v0.x, v0.y);
    __half2 h1 = __floats2half2_rn(v0.z, v0.w);
    __half2 h2 = __floats2half2_rn(v1.x, v1.y);
    __half2 h3 = __floats2half2_rn(v1.z, v1.w);
    ((uint4*)dst)[j] = make_uint4(*(uint32_t*)&h0, *(uint32_t*)&h1,
                                  *(uint32_t*)&h2, *(uint32_t*)&h3);
}

// ---- GEMM: C[M,N](fp32) = A @ B^T, plain fp16, K=768 ----
// 128x192 CTA tile, 8 warps as 2x4 (64x48 warp tiles), BK=64, 4-stage cp.async,
// ONE __syncthreads per iter, XOR-swizzled 128B smem rows.
template <bool QUANTUM>
__global__ __launch_bounds__(THREADS)
void mma_gemm(const __half* __restrict__ A,
              const __half* __restrict__ B,
              const float* __restrict__ bias,
              const float* __restrict__ theta,
              __half* __restrict__ E,
              float* __restrict__ out)
{
    extern __shared__ char smem[];
    const uint32_t sb = smem_u32(smem);
    const int tid = threadIdx.x;
    const int l = tid & 31;
    const int wid = tid >> 5;
    const int warp_m = wid & 1;    // 2 x 64 rows
    const int warp_n = wid >> 1;   // 4 x 48 cols
    const int bm = blockIdx.y * BM;
    const int bn = blockIdx.x * BN;

    float acc[4][6][4];
#pragma unroll
    for (int mi = 0; mi < 4; mi++)
#pragma unroll
        for (int ni = 0; ni < 6; ni++)
#pragma unroll
            for (int q = 0; q < 4; q++) acc[mi][ni][q] = 0.0f;

    // cooperative load: 2560 16B chunks/stage, 10 per thread
    auto load_stage = [&](int s, int k0) {
        uint32_t stage = sb + s * STAGE_B;
#pragma unroll
        for (int i = 0; i < 10; i++) {
            int id = tid + i * THREADS;
            int row = id >> 3;
            int c = id & 7;
            int cs = c ^ (row & 7);
            uint32_t dst = stage + row * 128 + cs * 16;
            const __half* g;
            if (row < AROWS) g = A + (size_t)(bm + row) * KD + k0 + c * 8;
            else             g = B + (size_t)(bn + row - AROWS) * KD + k0 + c * 8;
            cp_async16(dst, g);
        }
    };

    load_stage(0, 0);
    asm volatile("cp.async.commit_group;");
    load_stage(1, BK);
    asm volatile("cp.async.commit_group;");
    load_stage(2, 2 * BK);
    asm volatile("cp.async.commit_group;");

    // ldmatrix lane addressing within swizzled rows
    const int lr = l & 15;
    const int lc = l >> 4;
    const int lx = l & 7;

    for (int kt = 0; kt < NITER; kt++) {
        asm volatile("cp.async.wait_group 2;");
        __syncthreads();

        if (kt + 3 < NITER) load_stage((kt + 3) & 3, (kt + 3) * BK);
        asm volatile("cp.async.commit_group;");

        const uint32_t stage = sb + (kt & 3) * STAGE_B;
#pragma unroll
        for (int ksub = 0; ksub < 4; ksub++) {
            const int cs = (2 * ksub + lc) ^ lx;
            uint32_t a[4][4], b[3][4];
#pragma unroll
            for (int mi = 0; mi < 4; mi++) {
                int row = warp_m * 64 + mi * 16 + lr;
                ldsm4(a[mi], stage + row * 128 + cs * 16);
            }
#pragma unroll
            for (int q = 0; q < 3; q++) {
                int row = AROWS + warp_n * 48 + q * 16 + lr;
                ldsm4(b[q], stage + row * 128 + cs * 16);
            }
#pragma unroll
            for (int mi = 0; mi < 4; mi++)
#pragma unroll
                for (int q = 0; q < 3; q++) {
                    mma_f16(acc[mi][2 * q],     a[mi], b[q][0], b[q][2]);
                    mma_f16(acc[mi][2 * q + 1], a[mi], b[q][1], b[q][3]);
                }
        }
    }
    asm volatile("cp.async.wait_group 0;");
    __syncthreads();

    if (QUANTUM) {
        // stage accums through smem, then closed-form quantum head per 8-col group
        float* Cs = (float*)smem;
#pragma unroll
        for (int mi = 0; mi < 4; mi++)
#pragma unroll
            for (int ni = 0; ni < 6; ni++) {
                int row = warp_m * 64 + mi * 16 + (l >> 2);
                int col = warp_n * 48 + ni * 8 + (l & 3) * 2;
                *(float2*)&Cs[row * CPAD + col]       = make_float2(acc[mi][ni][0], acc[mi][ni][1]);
                *(float2*)&Cs[(row + 8) * CPAD + col] = make_float2(acc[mi][ni][2], acc[mi][ni][3]);
            }
        __syncthreads();

        float th[8];
#pragma unroll
        for (int j = 0; j < 8; j++) th[j] = theta[j];

        // 128 rows x 24 heads = 3072 tasks, 12 per thread
#pragma unroll
        for (int i = 0; i < 12; i++) {
            int g = tid + i * THREADS;
            int r = g / 24;
            int h = g - r * 24;
            int nn = bn + h * 8;
            const float* src = &Cs[r * CPAD + h * 8];
            float cc[8];
#pragma unroll
            for (int j = 0; j < 8; j++)
                cc[j] = cosf(src[j] + bias[nn + j] + th[j]);
            float o[8];
            float p = cc[0];
#pragma unroll
            for (int j = 1; j < 8; j++) { p *= cc[j]; o[j] = p; }
            float sp = cc[1];
#pragma unroll
            for (int j = 2; j < 8; j++) sp *= cc[j];
            o[0] = sp;
            uint32_t hv[4];
#pragma unroll
            for (int q = 0; q < 4; q++) {
                __half2 hh = __floats2half2_rn(o[2 * q], o[2 * q + 1]);
                hv[q] = *(uint32_t*)&hh;
            }
            *(uint4*)(E + (size_t)(bm + r) * KD + nn) = make_uint4(hv[0], hv[1], hv[2], hv[3]);
        }
    } else {
        // bias add + direct fp32 store
#pragma unroll
        for (int mi = 0; mi < 4; mi++)
#pragma unroll
            for (int ni = 0; ni < 6; ni++) {
                int row = bm + warp_m * 64 + mi * 16 + (l >> 2);
                int col = bn + warp_n * 48 + ni * 8 + (l & 3) * 2;
                float b0 = bias[col], b1 = bias[col + 1];
                *(float2*)&out[(size_t)row * N_DIM + col] =
                    make_float2(acc[mi][ni][0] + b0, acc[mi][ni][1] + b1);
                *(float2*)&out[(size_t)(row + 8) * N_DIM + col] =
                    make_float2(acc[mi][ni][2] + b0, acc[mi][ni][3] + b1);
            }
    }
}

extern "C" void kernel_launch(void* const* d_in, const int* in_sizes, int n_in,
                              void* d_out, int out_size)
{
    const float* x      = (const float*)d_in[0];
    const float* W_proj = (const float*)d_in[1];
    const float* b_proj = (const float*)d_in[2];
    const float* theta  = (const float*)d_in[3];
    const float* W_comb = (const float*)d_in[4];
    const float* b_comb = (const float*)d_in[5];
    float* out = (float*)d_out;

    cudaFuncSetAttribute(mma_gemm<true>,  cudaFuncAttributeMaxDynamicSharedMemorySize, SMEM_SZ);
    cudaFuncSetAttribute(mma_gemm<false>, cudaFuncAttributeMaxDynamicSharedMemorySize, SMEM_SZ);

    __half *A, *Bp, *Bc, *E;
    cudaGetSymbolAddress((void**)&A,  g_A);
    cudaGetSymbolAddress((void**)&Bp, g_Bp);
    cudaGetSymbolAddress((void**)&Bc, g_Bc);
    cudaGetSymbolAddress((void**)&E,  g_E);

    const int total8 = M_DIM * KD / 8 + 2 * (N_DIM * KD / 8);
    conv_kernel<<<(total8 + 255) / 256, 256>>>(x, W_proj, W_comb);

    dim3 grid(N_DIM / BN, M_DIM / BM);  // (4, 32) = 128 CTAs, single wave
    mma_gemm<true><<<grid, THREADS, SMEM_SZ>>>(A, Bp, b_proj, theta, E, nullptr);
    mma_gemm<false><<<grid, THREADS, SMEM_SZ>>>(E, Bc, b_comb, nullptr, nullptr, out);
}

// round 11
// speedup vs baseline: 7.1398x; 1.2526x over previous
#include <cuda_runtime.h>
#include <cuda_fp16.h>
#include <math.h>
#include <stdint.h>

// out = ((cos-product head)(x @ Wp^T + bp + theta)) @ Wc^T + bc
// Quantum head closed form (CNOT ring = linear XOR map on basis bits):
//   expz[w] = prod_{j=0..w} cos(ang_j)  (w>=1);  expz[0] = prod_{j=1..7} cos(ang_j)
//
// Tensor path: mma.sync m16n8k16 fp16 (HMMA; tcgen05 PTX rejected at sm_103 target).
// Both GEMMs plain fp16 (K=768), fp32 accumulate.
// Error ledger (measured R6-R10): combined fp16 truncation 5.7e-4 < 1e-3 gate.
// __cosf abs err ~2^-21 is negligible vs the 2^-12 truncation noise.

#define M_DIM 4096
#define N_DIM 768
#define KD    768
#define BM    128
#define BN    192
#define BK    64
#define NITER (KD / BK)        // 12
#define THREADS 256
#define NSTAGE 4

#define AROWS   BM
#define TROWS   (BM + BN)      // 320 rows per stage (A then B)
#define STAGE_B (TROWS * 128)  // 40960 (swizzled 128B rows)
#define SMEM_SZ (NSTAGE * STAGE_B)   // 163840
#define CPAD    (BN + 4)

// ---- device scratch (allocation-free rule) ----
__device__ __half g_A[(size_t)M_DIM * KD];
__device__ __half g_Bp[(size_t)N_DIM * KD];
__device__ __half g_Bc[(size_t)N_DIM * KD];
__device__ __half g_E[(size_t)M_DIM * KD];

// ---- helpers ----
__device__ __forceinline__ uint32_t smem_u32(const void* p) {
    uint32_t a;
    asm("{ .reg .u64 t; cvta.to.shared.u64 t, %1; cvt.u32.u64 %0, t; }" : "=r"(a) : "l"(p));
    return a;
}
__device__ __forceinline__ void cp_async16(uint32_t dst, const void* src) {
    asm volatile("cp.async.cg.shared.global [%0], [%1], 16;" :: "r"(dst), "l"(src));
}
__device__ __forceinline__ void ldsm4(uint32_t* r, uint32_t addr) {
    asm volatile("ldmatrix.sync.aligned.m8n8.x4.shared.b16 {%0,%1,%2,%3}, [%4];"
                 : "=r"(r[0]), "=r"(r[1]), "=r"(r[2]), "=r"(r[3]) : "r"(addr));
}
__device__ __forceinline__ void mma_f16(float* c, const uint32_t* a, uint32_t b0, uint32_t b1) {
    asm volatile(
        "mma.sync.aligned.m16n8k16.row.col.f32.f16.f16.f32 "
        "{%0,%1,%2,%3}, {%4,%5,%6,%7}, {%8,%9}, {%0,%1,%2,%3};"
        : "+f"(c[0]), "+f"(c[1]), "+f"(c[2]), "+f"(c[3])
        : "r"(a[0]), "r"(a[1]), "r"(a[2]), "r"(a[3]), "r"(b0), "r"(b1));
}

// ---- fp32 -> fp16 convert; 16 floats per thread (MLP=4), 2x16B stores ----
__global__ void conv_kernel(const float* __restrict__ x,
                            const float* __restrict__ wp,
                            const float* __restrict__ wc) {
    const int n16x = M_DIM * KD / 16;
    const int n16w = N_DIM * KD / 16;
    int i = blockIdx.x * blockDim.x + threadIdx.x;
    const float* src; __half* dst; int j;
    if (i < n16x)               { src = x;  dst = g_A;  j = i; }
    else if (i < n16x + n16w)   { src = wp; dst = g_Bp; j = i - n16x; }
    else if (i < n16x + 2*n16w) { src = wc; dst = g_Bc; j = i - n16x - n16w; }
    else return;
    float4 v0 = ((const float4*)src)[j * 4 + 0];
    float4 v1 = ((const float4*)src)[j * 4 + 1];
    float4 v2 = ((const float4*)src)[j * 4 + 2];
    float4 v3 = ((const float4*)src)[j * 4 + 3];
    __half2 h0 = __floats2half2_rn(v0.x, v0.y);
    __half2 h1 = __floats2half2_rn(v0.z, v0.w);
    __half2 h2 = __floats2half2_rn(v1.x, v1.y);
    __half2 h3 = __floats2half2_rn(v1.z, v1.w);
    __half2 h4 = __floats2half2_rn(v2.x, v2.y);
    __half2 h5 = __floats2half2_rn(v2.z, v2.w);
    __half2 h6 = __floats2half2_rn(v3.x, v3.y);
    __half2 h7 = __floats2half2_rn(v3.z, v3.w);
    ((uint4*)dst)[j * 2 + 0] = make_uint4(*(uint32_t*)&h0, *(uint32_t*)&h1,
                                          *(uint32_t*)&h2, *(uint32_t*)&h3);
    ((uint4*)dst)[j * 2 + 1] = make_uint4(*(uint32_t*)&h4, *(uint32_t*)&h5,
                                          *(uint32_t*)&h6, *(uint32_t*)&h7);
}

// ---- GEMM: C[M,N](fp32) = A @ B^T, plain fp16, K=768 ----
// 128x192 CTA tile, 8 warps as 2x4 (64x48 warp tiles), BK=64, 4-stage cp.async,
// ONE __syncthreads per iter, XOR-swizzled 128B smem rows.
template <bool QUANTUM>
__global__ __launch_bounds__(THREADS)
void mma_gemm(const __half* __restrict__ A,
              const __half* __restrict__ B,
              const float* __restrict__ bias,
              const float* __restrict__ theta,
              __half* __restrict__ E,
              float* __restrict__ out)
{
    extern __shared__ char smem[];
    const uint32_t sb = smem_u32(smem);
    const int tid = threadIdx.x;
    const int l = tid & 31;
    const int wid = tid >> 5;
    const int warp_m = wid & 1;    // 2 x 64 rows
    const int warp_n = wid >> 1;   // 4 x 48 cols
    const int bm = blockIdx.y * BM;
    const int bn = blockIdx.x * BN;

    float acc[4][6][4];
#pragma unroll
    for (int mi = 0; mi < 4; mi++)
#pragma unroll
        for (int ni = 0; ni < 6; ni++)
#pragma unroll
            for (int q = 0; q < 4; q++) acc[mi][ni][q] = 0.0f;

    // cooperative load: 2560 16B chunks/stage, 10 per thread
    auto load_stage = [&](int s, int k0) {
        uint32_t stage = sb + s * STAGE_B;
#pragma unroll
        for (int i = 0; i < 10; i++) {
            int id = tid + i * THREADS;
            int row = id >> 3;
            int c = id & 7;
            int cs = c ^ (row & 7);
            uint32_t dst = stage + row * 128 + cs * 16;
            const __half* g;
            if (row < AROWS) g = A + (size_t)(bm + row) * KD + k0 + c * 8;
            else             g = B + (size_t)(bn + row - AROWS) * KD + k0 + c * 8;
            cp_async16(dst, g);
        }
    };

    load_stage(0, 0);
    asm volatile("cp.async.commit_group;");
    load_stage(1, BK);
    asm volatile("cp.async.commit_group;");
    load_stage(2, 2 * BK);
    asm volatile("cp.async.commit_group;");

    // ldmatrix lane addressing within swizzled rows
    const int lr = l & 15;
    const int lc = l >> 4;
    const int lx = l & 7;

    for (int kt = 0; kt < NITER; kt++) {
        asm volatile("cp.async.wait_group 2;");
        __syncthreads();

        if (kt + 3 < NITER) load_stage((kt + 3) & 3, (kt + 3) * BK);
        asm volatile("cp.async.commit_group;");

        const uint32_t stage = sb + (kt & 3) * STAGE_B;
#pragma unroll
        for (int ksub = 0; ksub < 4; ksub++) {
            const int cs = (2 * ksub + lc) ^ lx;
            uint32_t a[4][4], b[3][4];
#pragma unroll
            for (int mi = 0; mi < 4; mi++) {
                int row = warp_m * 64 + mi * 16 + lr;
                ldsm4(a[mi], stage + row * 128 + cs * 16);
            }
#pragma unroll
            for (int q = 0; q < 3; q++) {
                int row = AROWS + warp_n * 48 + q * 16 + lr;
                ldsm4(b[q], stage + row * 128 + cs * 16);
            }
#pragma unroll
            for (int mi = 0; mi < 4; mi++)
#pragma unroll
                for (int q = 0; q < 3; q++) {
                    mma_f16(acc[mi][2 * q],     a[mi], b[q][0], b[q][2]);
                    mma_f16(acc[mi][2 * q + 1], a[mi], b[q][1], b[q][3]);
                }
        }
    }
    asm volatile("cp.async.wait_group 0;");
    __syncthreads();

    if (QUANTUM) {
        // stage accums through smem, then closed-form quantum head per 8-col group
        float* Cs = (float*)smem;
#pragma unroll
        for (int mi = 0; mi < 4; mi++)
#pragma unroll
            for (int ni = 0; ni < 6; ni++) {
                int row = warp_m * 64 + mi * 16 + (l >> 2);
                int col = warp_n * 48 + ni * 8 + (l & 3) * 2;
                *(float2*)&Cs[row * CPAD + col]       = make_float2(acc[mi][ni][0], acc[mi][ni][1]);
                *(float2*)&Cs[(row + 8) * CPAD + col] = make_float2(acc[mi][ni][2], acc[mi][ni][3]);
            }
        __syncthreads();

        float th[8];
#pragma unroll
        for (int j = 0; j < 8; j++) th[j] = theta[j];

        // 128 rows x 24 heads = 3072 tasks, 12 per thread
#pragma unroll
        for (int i = 0; i < 12; i++) {
            int g = tid + i * THREADS;
            int r = g / 24;
            int h = g - r * 24;
            int nn = bn + h * 8;
            const float* src = &Cs[r * CPAD + h * 8];
            float cc[8];
#pragma unroll
            for (int j = 0; j < 8; j++)
                cc[j] = __cosf(src[j] + bias[nn + j] + th[j]);
            float o[8];
            float p = cc[0];
#pragma unroll
            for (int j = 1; j < 8; j++) { p *= cc[j]; o[j] = p; }
            float sp = cc[1];
#pragma unroll
            for (int j = 2; j < 8; j++) sp *= cc[j];
            o[0] = sp;
            uint32_t hv[4];
#pragma unroll
            for (int q = 0; q < 4; q++) {
                __half2 hh = __floats2half2_rn(o[2 * q], o[2 * q + 1]);
                hv[q] = *(uint32_t*)&hh;
            }
            *(uint4*)(E + (size_t)(bm + r) * KD + nn) = make_uint4(hv[0], hv[1], hv[2], hv[3]);
        }
    } else {
        // bias add + direct fp32 store
#pragma unroll
        for (int mi = 0; mi < 4; mi++)
#pragma unroll
            for (int ni = 0; ni < 6; ni++) {
                int row = bm + warp_m * 64 + mi * 16 + (l >> 2);
                int col = bn + warp_n * 48 + ni * 8 + (l & 3) * 2;
                float b0 = bias[col], b1 = bias[col + 1];
                *(float2*)&out[(size_t)row * N_DIM + col] =
                    make_float2(acc[mi][ni][0] + b0, acc[mi][ni][1] + b1);
                *(float2*)&out[(size_t)(row + 8) * N_DIM + col] =
                    make_float2(acc[mi][ni][2] + b0, acc[mi][ni][3] + b1);
            }
    }
}

extern "C" void kernel_launch(void* const* d_in, const int* in_sizes, int n_in,
                              void* d_out, int out_size)
{
    const float* x      = (const float*)d_in[0];
    const float* W_proj = (const float*)d_in[1];
    const float* b_proj = (const float*)d_in[2];
    const float* theta  = (const float*)d_in[3];
    const float* W_comb = (const float*)d_in[4];
    const float* b_comb = (const float*)d_in[5];
    float* out = (float*)d_out;

    cudaFuncSetAttribute(mma_gemm<true>,  cudaFuncAttributeMaxDynamicSharedMemorySize, SMEM_SZ);
    cudaFuncSetAttribute(mma_gemm<false>, cudaFuncAttributeMaxDynamicSharedMemorySize, SMEM_SZ);

    __half *A, *Bp, *Bc, *E;
    cudaGetSymbolAddress((void**)&A,  g_A);
    cudaGetSymbolAddress((void**)&Bp, g_Bp);
    cudaGetSymbolAddress((void**)&Bc, g_Bc);
    cudaGetSymbolAddress((void**)&E,  g_E);

    const int total16 = M_DIM * KD / 16 + 2 * (N_DIM * KD / 16);
    conv_kernel<<<(total16 + 255) / 256, 256>>>(x, W_proj, W_comb);

    dim3 grid(N_DIM / BN, M_DIM / BM);  // (4, 32) = 128 CTAs, single wave
    mma_gemm<true><<<grid, THREADS, SMEM_SZ>>>(A, Bp, b_proj, theta, E, nullptr);
    mma_gemm<false><<<grid, THREADS, SMEM_SZ>>>(E, Bc, b_comb, nullptr, nullptr, out);
}